// round 1
// baseline (speedup 1.0000x reference)
#include <cuda_runtime.h>
#include <math.h>

#define T  2048
#define H  2048
#define NH 16
#define HD 128
#define NE 16
#define II 2048
#define I2 4096
#define EPS 1e-6f

#define BM 64
#define BN 64
#define BK 16

// ---------------- scratch (static device memory; no allocs) ----------------
__device__ float g_h[(size_t)T * H];
__device__ float g_qkv[(size_t)T * 3 * H];
__device__ float g_S[(size_t)NH * T * T];
__device__ float g_attn[(size_t)T * H];
__device__ float g_tmp[(size_t)T * H];
__device__ float g_x2[(size_t)T * H];
__device__ float g_h2[(size_t)T * H];
__device__ float g_logits[(size_t)T * NE];
__device__ float g_topw[T];
__device__ int   g_topi[T];
__device__ int   g_counts[NE];
__device__ int   g_rows[(size_t)NE * T];
__device__ float g_gu[(size_t)T * I2];
__device__ float g_act[(size_t)T * II];
__device__ float g_moe[(size_t)T * H];
__device__ float g_sgu[(size_t)T * I2];
__device__ float g_sact[(size_t)T * II];
__device__ float g_shr[(size_t)T * H];

// ---------------- block reductions ----------------
__device__ __forceinline__ float blk_sum(float v) {
    __shared__ float sh[33];
    __syncthreads();
    int lane = threadIdx.x & 31, w = threadIdx.x >> 5;
#pragma unroll
    for (int o = 16; o; o >>= 1) v += __shfl_xor_sync(0xffffffffu, v, o);
    if (lane == 0) sh[w] = v;
    __syncthreads();
    if (threadIdx.x < 32) {
        int nw = (blockDim.x + 31) >> 5;
        float r = (threadIdx.x < nw) ? sh[threadIdx.x] : 0.f;
#pragma unroll
        for (int o = 16; o; o >>= 1) r += __shfl_xor_sync(0xffffffffu, r, o);
        if (threadIdx.x == 0) sh[32] = r;
    }
    __syncthreads();
    return sh[32];
}

__device__ __forceinline__ float blk_max(float v) {
    __shared__ float sh[33];
    __syncthreads();
    int lane = threadIdx.x & 31, w = threadIdx.x >> 5;
#pragma unroll
    for (int o = 16; o; o >>= 1) v = fmaxf(v, __shfl_xor_sync(0xffffffffu, v, o));
    if (lane == 0) sh[w] = v;
    __syncthreads();
    if (threadIdx.x < 32) {
        int nw = (blockDim.x + 31) >> 5;
        float r = (threadIdx.x < nw) ? sh[threadIdx.x] : -3.4e38f;
#pragma unroll
        for (int o = 16; o; o >>= 1) r = fmaxf(r, __shfl_xor_sync(0xffffffffu, r, o));
        if (threadIdx.x == 0) sh[32] = r;
    }
    __syncthreads();
    return sh[32];
}

// ---------------- rmsnorm over rows of [rows, ncols] ----------------
__global__ void rmsnorm_kernel(const float* __restrict__ x, const float* __restrict__ w,
                               float* __restrict__ out, int ncols) {
    int row = blockIdx.x;
    const float* xr = x + (size_t)row * ncols;
    float ss = 0.f;
    for (int i = threadIdx.x; i < ncols; i += blockDim.x) {
        float v = xr[i];
        ss += v * v;
    }
    float tot = blk_sum(ss);
    float inv = rsqrtf(tot / (float)ncols + EPS);
    float* orow = out + (size_t)row * ncols;
    for (int i = threadIdx.x; i < ncols; i += blockDim.x)
        orow[i] = xr[i] * inv * w[i];
}

// ---------------- GEMM NT: C[m,n] = sum_k A[m,k]*B[n,k] (optionally row-gathered A/C)
__global__ void __launch_bounds__(256) gemm_nt(
    const float* __restrict__ A, int lda, long long sA,
    const float* __restrict__ B, int ldb, long long sB,
    float* __restrict__ C, int ldc, long long sC,
    int M, int N, int K,
    const int* __restrict__ rowsAll, const int* __restrict__ cntAll)
{
    int z = blockIdx.z;
    A += (size_t)z * sA;
    B += (size_t)z * sB;
    C += (size_t)z * sC;
    const int* rows = rowsAll ? (rowsAll + (size_t)z * M) : 0;
    int Mv = cntAll ? cntAll[z] : M;
    int m0 = blockIdx.y * BM;
    if (m0 >= Mv) return;
    int n0 = blockIdx.x * BN;

    __shared__ float As[BK][BM + 1];
    __shared__ float Bs[BK][BN + 1];
    __shared__ int rid[BM];

    int tid = threadIdx.x;
    if (tid < BM) {
        int gm = m0 + tid;
        rid[tid] = rows ? (gm < Mv ? rows[gm] : -1) : gm;
    }
    __syncthreads();

    int lm = tid >> 2;        // 0..63
    int lk = (tid & 3) << 2;  // 0,4,8,12
    int r = rid[lm];
    bool avalid = (r >= 0);
    const float* Arow = A + (size_t)(avalid ? r : 0) * lda;
    const float* Brow = B + (size_t)(n0 + lm) * ldb;

    int ty = tid >> 4, tx = tid & 15;
    float acc[4][4];
#pragma unroll
    for (int i = 0; i < 4; i++)
#pragma unroll
        for (int j = 0; j < 4; j++) acc[i][j] = 0.f;

    for (int kt = 0; kt < K; kt += BK) {
        float4 av = avalid ? *(const float4*)(Arow + kt + lk) : make_float4(0.f, 0.f, 0.f, 0.f);
        float4 bv = *(const float4*)(Brow + kt + lk);
        __syncthreads();
        As[lk + 0][lm] = av.x; As[lk + 1][lm] = av.y; As[lk + 2][lm] = av.z; As[lk + 3][lm] = av.w;
        Bs[lk + 0][lm] = bv.x; Bs[lk + 1][lm] = bv.y; Bs[lk + 2][lm] = bv.z; Bs[lk + 3][lm] = bv.w;
        __syncthreads();
#pragma unroll
        for (int k = 0; k < BK; k++) {
            float a0 = As[k][ty * 4 + 0], a1 = As[k][ty * 4 + 1];
            float a2 = As[k][ty * 4 + 2], a3 = As[k][ty * 4 + 3];
            float b0 = Bs[k][tx * 4 + 0], b1 = Bs[k][tx * 4 + 1];
            float b2 = Bs[k][tx * 4 + 2], b3 = Bs[k][tx * 4 + 3];
            acc[0][0] += a0 * b0; acc[0][1] += a0 * b1; acc[0][2] += a0 * b2; acc[0][3] += a0 * b3;
            acc[1][0] += a1 * b0; acc[1][1] += a1 * b1; acc[1][2] += a1 * b2; acc[1][3] += a1 * b3;
            acc[2][0] += a2 * b0; acc[2][1] += a2 * b1; acc[2][2] += a2 * b2; acc[2][3] += a2 * b3;
            acc[3][0] += a3 * b0; acc[3][1] += a3 * b1; acc[3][2] += a3 * b2; acc[3][3] += a3 * b3;
        }
    }
#pragma unroll
    for (int i = 0; i < 4; i++) {
        int rr = rid[ty * 4 + i];
        if (rr < 0) continue;
        float* Cr = C + (size_t)rr * ldc + n0 + tx * 4;
        *(float4*)Cr = make_float4(acc[i][0], acc[i][1], acc[i][2], acc[i][3]);
    }
}

// ---------------- GEMM NN: C[m,n] = sum_k A[m,k]*B[k,n] ----------------
__global__ void __launch_bounds__(256) gemm_nn(
    const float* __restrict__ A, int lda, long long sA,
    const float* __restrict__ B, int ldb, long long sB,
    float* __restrict__ C, int ldc, long long sC,
    int M, int N, int K)
{
    int z = blockIdx.z;
    A += (size_t)z * sA;
    B += (size_t)z * sB;
    C += (size_t)z * sC;
    int m0 = blockIdx.y * BM;
    int n0 = blockIdx.x * BN;

    __shared__ float As[BK][BM + 1];
    __shared__ float Bs[BK][BN + 1];

    int tid = threadIdx.x;
    int lm = tid >> 2;
    int lk = (tid & 3) << 2;
    const float* Arow = A + (size_t)(m0 + lm) * lda;

    int bn = tid & 63;        // 0..63 (col within tile)
    int kq = (tid >> 6) << 2; // 0,4,8,12

    int ty = tid >> 4, tx = tid & 15;
    float acc[4][4];
#pragma unroll
    for (int i = 0; i < 4; i++)
#pragma unroll
        for (int j = 0; j < 4; j++) acc[i][j] = 0.f;

    for (int kt = 0; kt < K; kt += BK) {
        float4 av = *(const float4*)(Arow + kt + lk);
        float bv0 = B[(size_t)(kt + kq + 0) * ldb + n0 + bn];
        float bv1 = B[(size_t)(kt + kq + 1) * ldb + n0 + bn];
        float bv2 = B[(size_t)(kt + kq + 2) * ldb + n0 + bn];
        float bv3 = B[(size_t)(kt + kq + 3) * ldb + n0 + bn];
        __syncthreads();
        As[lk + 0][lm] = av.x; As[lk + 1][lm] = av.y; As[lk + 2][lm] = av.z; As[lk + 3][lm] = av.w;
        Bs[kq + 0][bn] = bv0; Bs[kq + 1][bn] = bv1; Bs[kq + 2][bn] = bv2; Bs[kq + 3][bn] = bv3;
        __syncthreads();
#pragma unroll
        for (int k = 0; k < BK; k++) {
            float a0 = As[k][ty * 4 + 0], a1 = As[k][ty * 4 + 1];
            float a2 = As[k][ty * 4 + 2], a3 = As[k][ty * 4 + 3];
            float b0 = Bs[k][tx * 4 + 0], b1 = Bs[k][tx * 4 + 1];
            float b2 = Bs[k][tx * 4 + 2], b3 = Bs[k][tx * 4 + 3];
            acc[0][0] += a0 * b0; acc[0][1] += a0 * b1; acc[0][2] += a0 * b2; acc[0][3] += a0 * b3;
            acc[1][0] += a1 * b0; acc[1][1] += a1 * b1; acc[1][2] += a1 * b2; acc[1][3] += a1 * b3;
            acc[2][0] += a2 * b0; acc[2][1] += a2 * b1; acc[2][2] += a2 * b2; acc[2][3] += a2 * b3;
            acc[3][0] += a3 * b0; acc[3][1] += a3 * b1; acc[3][2] += a3 * b2; acc[3][3] += a3 * b3;
        }
    }
#pragma unroll
    for (int i = 0; i < 4; i++) {
        float* Cr = C + (size_t)(m0 + ty * 4 + i) * ldc + n0 + tx * 4;
        *(float4*)Cr = make_float4(acc[i][0], acc[i][1], acc[i][2], acc[i][3]);
    }
}

// ---------------- per-head q/k rmsnorm + rope (in-place on qkv) ----------------
__global__ void qk_norm_rope(float* __restrict__ qkv,
                             const float* __restrict__ qw, const float* __restrict__ kw) {
    int t = blockIdx.x, h = blockIdx.y, which = blockIdx.z;  // 0=q, 1=k
    float* base = qkv + (size_t)t * (3 * H) + (size_t)which * H + (size_t)h * HD;
    int d = threadIdx.x;  // 128 threads
    float v = base[d];
    float tot = blk_sum(v * v);
    float inv = rsqrtf(tot / (float)HD + EPS);
    const float* w = which ? kw : qw;
    float nv = v * inv * w[d];
    __shared__ float buf[HD];
    buf[d] = nv;
    __syncthreads();
    if (d < HD / 2) {
        int i = d;
        double invf = pow(10000.0, -2.0 * (double)i / (double)HD);
        double ang = (double)t * invf;
        float c = (float)cos(ang), s = (float)sin(ang);
        float t1 = buf[2 * i], t2 = buf[2 * i + 1];
        base[2 * i]     = t1 * c - t2 * s;
        base[2 * i + 1] = t1 * s + t2 * c;
    }
}

// ---------------- causal softmax on S[h][t][:] ----------------
__global__ void softmax_causal(float* __restrict__ S) {
    int t = blockIdx.x, h = blockIdx.y;
    float* row = S + ((size_t)h * T + t) * T;
    int n = t + 1;
    const float scale = 0.08838834764831845f;  // 1/sqrt(128)
    float mx = -3.4e38f;
    for (int j = threadIdx.x; j < n; j += blockDim.x)
        mx = fmaxf(mx, row[j] * scale);
    mx = blk_max(mx);
    float sum = 0.f;
    for (int j = threadIdx.x; j < n; j += blockDim.x) {
        float e = expf(row[j] * scale - mx);
        row[j] = e;
        sum += e;
    }
    sum = blk_sum(sum);
    float invs = 1.f / sum;
    for (int j = threadIdx.x; j < n; j += blockDim.x) row[j] *= invs;
    for (int j = n + (int)threadIdx.x; j < T; j += blockDim.x) row[j] = 0.f;
}

// ---------------- elementwise ----------------
__global__ void add2(const float* __restrict__ a, const float* __restrict__ b,
                     float* __restrict__ c, int n) {
    int i = blockIdx.x * blockDim.x + threadIdx.x;
    if (i < n) c[i] = a[i] + b[i];
}

__global__ void silu_mul(const float* __restrict__ gu, float* __restrict__ act) {
    int idx = blockIdx.x * blockDim.x + threadIdx.x;
    if (idx >= T * II) return;
    int t = idx / II, i = idx % II;
    float g = gu[(size_t)t * I2 + i];
    float u = gu[(size_t)t * I2 + II + i];
    act[(size_t)t * II + i] = (g / (1.f + expf(-g))) * u;
}

__global__ void final_out(const float* __restrict__ x2, const float* __restrict__ moe,
                          const float* __restrict__ topw, const float* __restrict__ shr,
                          float* __restrict__ out, int n) {
    int i = blockIdx.x * blockDim.x + threadIdx.x;
    if (i < n) {
        int t = i / H;
        out[i] = x2[i] + moe[i] * topw[t] + shr[i];
    }
}

// ---------------- gate logits + top-1 routing ----------------
__global__ void gate_logits(const float* __restrict__ h2, const float* __restrict__ gw,
                            float* __restrict__ logits) {
    int t = blockIdx.x;
    __shared__ float xs[H];
    for (int i = threadIdx.x; i < H; i += blockDim.x) xs[i] = h2[(size_t)t * H + i];
    __syncthreads();
    int warp = threadIdx.x >> 5, lane = threadIdx.x & 31;
    for (int e = warp; e < NE; e += (blockDim.x >> 5)) {
        const float* w = gw + (size_t)e * H;
        float s = 0.f;
        for (int k = lane; k < H; k += 32) s += xs[k] * w[k];
#pragma unroll
        for (int o = 16; o; o >>= 1) s += __shfl_xor_sync(0xffffffffu, s, o);
        if (lane == 0) logits[(size_t)t * NE + e] = s;
    }
}

__global__ void route_topk(const float* __restrict__ logits, float* __restrict__ topw,
                           int* __restrict__ topi) {
    int t = blockIdx.x * blockDim.x + threadIdx.x;
    if (t >= T) return;
    float mx = -3.4e38f;
    int mi = 0;
#pragma unroll
    for (int e = 0; e < NE; e++) {
        float l = logits[(size_t)t * NE + e];
        if (l > mx) { mx = l; mi = e; }
    }
    float s = 0.f;
#pragma unroll
    for (int e = 0; e < NE; e++) s += expf(logits[(size_t)t * NE + e] - mx);
    topw[t] = 1.f / s;
    topi[t] = mi;
}

__global__ void zero_counts(int* c) {
    if (threadIdx.x < NE) c[threadIdx.x] = 0;
}

__global__ void build_route(const int* __restrict__ topi, int* __restrict__ counts,
                            int* __restrict__ rows) {
    int t = blockIdx.x * blockDim.x + threadIdx.x;
    if (t >= T) return;
    int e = topi[t];
    int p = atomicAdd(&counts[e], 1);
    rows[(size_t)e * T + p] = t;
}

// ---------------- host ----------------
#define SYM(p, s) do { void* _v; cudaGetSymbolAddress(&_v, s); p = (decltype(p))_v; } while (0)

extern "C" void kernel_launch(void* const* d_in, const int* in_sizes, int n_in,
                              void* d_out, int out_size) {
    const float* x      = (const float*)d_in[0];
    const float* ln1    = (const float*)d_in[1];
    const float* qkv_w  = (const float*)d_in[2];
    const float* qlnw   = (const float*)d_in[3];
    const float* klnw   = (const float*)d_in[4];
    const float* o_w    = (const float*)d_in[5];
    const float* ln2    = (const float*)d_in[6];
    const float* gate_w = (const float*)d_in[7];
    const float* egu    = (const float*)d_in[8];
    const float* edown  = (const float*)d_in[9];
    const float* sguw   = (const float*)d_in[10];
    const float* sdw    = (const float*)d_in[11];
    float* out = (float*)d_out;

    float *h, *qkv, *S, *attn, *tmp, *x2, *h2, *logits, *topw, *gu, *act, *moe, *sgu, *sact, *shr;
    int *topi, *counts, *rows;
    SYM(h, g_h); SYM(qkv, g_qkv); SYM(S, g_S); SYM(attn, g_attn); SYM(tmp, g_tmp);
    SYM(x2, g_x2); SYM(h2, g_h2); SYM(logits, g_logits); SYM(topw, g_topw);
    SYM(gu, g_gu); SYM(act, g_act); SYM(moe, g_moe); SYM(sgu, g_sgu); SYM(sact, g_sact);
    SYM(shr, g_shr); SYM(topi, g_topi); SYM(counts, g_counts); SYM(rows, g_rows);

    // 1. h = rmsnorm(x, ln1)
    rmsnorm_kernel<<<T, 256>>>(x, ln1, h, H);
    // 2. qkv = h @ qkv_w^T   [T, 6144]
    gemm_nt<<<dim3(3 * H / BN, T / BM, 1), 256>>>(h, H, 0, qkv_w, H, 0, qkv, 3 * H, 0,
                                                  T, 3 * H, H, 0, 0);
    // 3. per-head q/k rmsnorm + rope (in-place)
    qk_norm_rope<<<dim3(T, NH, 2), HD>>>(qkv, qlnw, klnw);
    // 4. S[h] = Q[h] @ K[h]^T   (batched over heads)
    gemm_nt<<<dim3(T / BN, T / BM, NH), 256>>>(qkv, 3 * H, HD, qkv + H, 3 * H, HD,
                                               S, T, (long long)T * T, T, T, HD, 0, 0);
    // 5. causal softmax (with 1/sqrt(HD) scale)
    softmax_causal<<<dim3(T, NH), 256>>>(S);
    // 6. attn[h] = P[h] @ V[h]
    gemm_nn<<<dim3(HD / BN, T / BM, NH), 256>>>(S, T, (long long)T * T, qkv + 2 * H, 3 * H, HD,
                                                attn, H, HD, T, HD, T);
    // 7. tmp = attn @ o_w^T ; x2 = x + tmp
    gemm_nt<<<dim3(H / BN, T / BM, 1), 256>>>(attn, H, 0, o_w, H, 0, tmp, H, 0, T, H, H, 0, 0);
    add2<<<(T * H + 255) / 256, 256>>>(x, tmp, x2, T * H);
    // 8. h2 = rmsnorm(x2, ln2)
    rmsnorm_kernel<<<T, 256>>>(x2, ln2, h2, H);
    // 9. routing
    gate_logits<<<T, 256>>>(h2, gate_w, logits);
    route_topk<<<(T + 255) / 256, 256>>>(logits, topw, topi);
    zero_counts<<<1, 32>>>(counts);
    build_route<<<(T + 255) / 256, 256>>>(topi, counts, rows);
    // 10. MoE (top-1): gather tokens per expert, gemm per expert batched over z
    gemm_nt<<<dim3(I2 / BN, T / BM, NE), 256>>>(h2, H, 0, egu, H, (long long)I2 * H,
                                                gu, I2, 0, T, I2, H, rows, counts);
    silu_mul<<<(T * II + 255) / 256, 256>>>(gu, act);
    gemm_nt<<<dim3(H / BN, T / BM, NE), 256>>>(act, II, 0, edown, II, (long long)H * II,
                                               moe, H, 0, T, H, II, rows, counts);
    // 11. shared FFN
    gemm_nt<<<dim3(I2 / BN, T / BM, 1), 256>>>(h2, H, 0, sguw, H, 0, sgu, I2, 0, T, I2, H, 0, 0);
    silu_mul<<<(T * II + 255) / 256, 256>>>(sgu, sact);
    gemm_nt<<<dim3(H / BN, T / BM, 1), 256>>>(sact, II, 0, sdw, II, 0, shr, H, 0, T, H, II, 0, 0);
    // 12. out = x2 + moe*topw + shared
    final_out<<<(T * H + 255) / 256, 256>>>(x2, moe, topw, shr, out, T * H);
}

// round 2
// speedup vs baseline: 2.7585x; 2.7585x over previous
#include <cuda_runtime.h>
#include <math.h>
#include <stdint.h>

#define T  2048
#define H  2048
#define NH 16
#define HD 128
#define NE 16
#define II 2048
#define I2 4096
#define EPS 1e-6f

// mma tile config
#define TBM 128
#define TBN 128
#define TBK 32
#define ASTR 36                 // TBK + 4 pad (floats)
#define ATILE (TBM * ASTR)      // 4608 floats
#define BSTR_NN 136             // TBN + 8 pad for NN B tile
#define BTILE_NN (TBK * BSTR_NN) // 4352 floats

// ---------------- scratch ----------------
__device__ float g_h[(size_t)T * H];
__device__ float g_qkv[(size_t)T * 3 * H];
__device__ float g_S[(size_t)NH * T * T];
__device__ float g_attn[(size_t)T * H];
__device__ float g_tmp[(size_t)T * H];
__device__ float g_x2[(size_t)T * H];
__device__ float g_h2[(size_t)T * H];
__device__ float g_logits[(size_t)T * NE];
__device__ float g_topw[T];
__device__ int   g_topi[T];
__device__ int   g_counts[NE];
__device__ int   g_rows[(size_t)NE * T];
__device__ float g_gu[(size_t)T * I2];
__device__ float g_act[(size_t)T * II];
__device__ float g_moe[(size_t)T * H];
__device__ float g_sgu[(size_t)T * I2];
__device__ float g_sact[(size_t)T * II];
__device__ float g_shr[(size_t)T * H];

// ---------------- helpers ----------------
__device__ __forceinline__ uint32_t f2tf(float x) {
    uint32_t u;
    asm("cvt.rna.tf32.f32 %0, %1;" : "=r"(u) : "f"(x));
    return u;
}

__device__ __forceinline__ void mma_tf32(float c[4], const uint32_t a[4], const uint32_t b[2]) {
    asm volatile("mma.sync.aligned.m16n8k8.row.col.f32.tf32.tf32.f32 "
                 "{%0,%1,%2,%3}, {%4,%5,%6,%7}, {%8,%9}, {%0,%1,%2,%3};"
                 : "+f"(c[0]), "+f"(c[1]), "+f"(c[2]), "+f"(c[3])
                 : "r"(a[0]), "r"(a[1]), "r"(a[2]), "r"(a[3]), "r"(b[0]), "r"(b[1]));
}

__device__ __forceinline__ float blk_sum(float v) {
    __shared__ float sh[33];
    __syncthreads();
    int lane = threadIdx.x & 31, w = threadIdx.x >> 5;
#pragma unroll
    for (int o = 16; o; o >>= 1) v += __shfl_xor_sync(0xffffffffu, v, o);
    if (lane == 0) sh[w] = v;
    __syncthreads();
    if (threadIdx.x < 32) {
        int nw = (blockDim.x + 31) >> 5;
        float r = (threadIdx.x < nw) ? sh[threadIdx.x] : 0.f;
#pragma unroll
        for (int o = 16; o; o >>= 1) r += __shfl_xor_sync(0xffffffffu, r, o);
        if (threadIdx.x == 0) sh[32] = r;
    }
    __syncthreads();
    return sh[32];
}

__device__ __forceinline__ float blk_max(float v) {
    __shared__ float sh[33];
    __syncthreads();
    int lane = threadIdx.x & 31, w = threadIdx.x >> 5;
#pragma unroll
    for (int o = 16; o; o >>= 1) v = fmaxf(v, __shfl_xor_sync(0xffffffffu, v, o));
    if (lane == 0) sh[w] = v;
    __syncthreads();
    if (threadIdx.x < 32) {
        int nw = (blockDim.x + 31) >> 5;
        float r = (threadIdx.x < nw) ? sh[threadIdx.x] : -3.4e38f;
#pragma unroll
        for (int o = 16; o; o >>= 1) r = fmaxf(r, __shfl_xor_sync(0xffffffffu, r, o));
        if (threadIdx.x == 0) sh[32] = r;
    }
    __syncthreads();
    return sh[32];
}

// ---------------- tf32 GEMM NT: C[m,n] = sum_k A[m,k] * B[n,k] ----------------
// optional row-gather on A/C via rowsAll/cntAll (per z slice)
__global__ void __launch_bounds__(256) mma_nt(
    const float* __restrict__ A, int lda, long long sA,
    const float* __restrict__ B, int ldb, long long sB,
    float* __restrict__ C, int ldc, long long sC,
    int M, int N, int K,
    const int* __restrict__ rowsAll, const int* __restrict__ cntAll)
{
    extern __shared__ float smem[];
    float* As = smem;                 // 2 * ATILE
    float* Bs = smem + 2 * ATILE;     // 2 * ATILE
    __shared__ int rid[TBM];

    int z = blockIdx.z;
    A += (size_t)z * sA; B += (size_t)z * sB; C += (size_t)z * sC;
    const int* rows = rowsAll ? rowsAll + (size_t)z * M : 0;
    int Mv = cntAll ? cntAll[z] : M;
    int m0 = blockIdx.y * TBM;
    if (m0 >= Mv) return;
    int n0 = blockIdx.x * TBN;

    int tid = threadIdx.x;
    if (tid < TBM) {
        int gm = m0 + tid;
        rid[tid] = rows ? (gm < Mv ? rows[gm] : -1) : gm;
    }
    __syncthreads();

    // loader mapping: 1024 float4 per tile, 4 per thread
    int lrow[4], lcol[4], ra[4];
#pragma unroll
    for (int i = 0; i < 4; i++) {
        int idx = tid + i * 256;
        lrow[i] = idx >> 3;
        lcol[i] = (idx & 7) * 4;
        ra[i] = rid[lrow[i]];
    }

    float4 rA[4], rB[4];
    const float4 z4 = make_float4(0.f, 0.f, 0.f, 0.f);

    // prologue: load tile kt=0
#pragma unroll
    for (int i = 0; i < 4; i++) {
        rA[i] = (ra[i] >= 0) ? *(const float4*)(A + (size_t)ra[i] * lda + lcol[i]) : z4;
        rB[i] = *(const float4*)(B + (size_t)(n0 + lrow[i]) * ldb + lcol[i]);
    }
#pragma unroll
    for (int i = 0; i < 4; i++) {
        int base = lrow[i] * ASTR + lcol[i];
        *(uint4*)(As + base) = make_uint4(f2tf(rA[i].x), f2tf(rA[i].y), f2tf(rA[i].z), f2tf(rA[i].w));
        *(uint4*)(Bs + base) = make_uint4(f2tf(rB[i].x), f2tf(rB[i].y), f2tf(rB[i].z), f2tf(rB[i].w));
    }
    __syncthreads();

    int lane = tid & 31, wid = tid >> 5;
    int wm = (wid & 1) * 64, wn = (wid >> 1) * 32;
    int g = lane >> 2, cc = lane & 3;

    float acc[4][4][4];
#pragma unroll
    for (int mi = 0; mi < 4; mi++)
#pragma unroll
        for (int ni = 0; ni < 4; ni++)
#pragma unroll
            for (int j = 0; j < 4; j++) acc[mi][ni][j] = 0.f;

    int buf = 0;
    for (int kt = TBK; kt <= K; kt += TBK) {
        bool has_next = kt < K;
        if (has_next) {
#pragma unroll
            for (int i = 0; i < 4; i++) {
                rA[i] = (ra[i] >= 0) ? *(const float4*)(A + (size_t)ra[i] * lda + kt + lcol[i]) : z4;
                rB[i] = *(const float4*)(B + (size_t)(n0 + lrow[i]) * ldb + kt + lcol[i]);
            }
        }
        const uint32_t* ab = (const uint32_t*)(As + buf * ATILE);
        const uint32_t* bb = (const uint32_t*)(Bs + buf * ATILE);
#pragma unroll
        for (int kk = 0; kk < TBK; kk += 8) {
            uint32_t af[4][4], bf[4][2];
#pragma unroll
            for (int mi = 0; mi < 4; mi++) {
                int r = wm + mi * 16 + g;
                af[mi][0] = ab[r * ASTR + kk + cc];
                af[mi][1] = ab[(r + 8) * ASTR + kk + cc];
                af[mi][2] = ab[r * ASTR + kk + cc + 4];
                af[mi][3] = ab[(r + 8) * ASTR + kk + cc + 4];
            }
#pragma unroll
            for (int ni = 0; ni < 4; ni++) {
                int n = wn + ni * 8 + g;
                bf[ni][0] = bb[n * ASTR + kk + cc];
                bf[ni][1] = bb[n * ASTR + kk + cc + 4];
            }
#pragma unroll
            for (int mi = 0; mi < 4; mi++)
#pragma unroll
                for (int ni = 0; ni < 4; ni++)
                    mma_tf32(acc[mi][ni], af[mi], bf[ni]);
        }
        if (has_next) {
            float* an = As + (buf ^ 1) * ATILE;
            float* bn = Bs + (buf ^ 1) * ATILE;
#pragma unroll
            for (int i = 0; i < 4; i++) {
                int base = lrow[i] * ASTR + lcol[i];
                *(uint4*)(an + base) = make_uint4(f2tf(rA[i].x), f2tf(rA[i].y), f2tf(rA[i].z), f2tf(rA[i].w));
                *(uint4*)(bn + base) = make_uint4(f2tf(rB[i].x), f2tf(rB[i].y), f2tf(rB[i].z), f2tf(rB[i].w));
            }
            __syncthreads();
            buf ^= 1;
        }
    }

    // epilogue
#pragma unroll
    for (int mi = 0; mi < 4; mi++) {
        int r0 = wm + mi * 16 + g;
        int rr = rid[r0], rr8 = rid[r0 + 8];
#pragma unroll
        for (int ni = 0; ni < 4; ni++) {
            int col = n0 + wn + ni * 8 + cc * 2;
            if (rr >= 0)
                *(float2*)(C + (size_t)rr * ldc + col) = make_float2(acc[mi][ni][0], acc[mi][ni][1]);
            if (rr8 >= 0)
                *(float2*)(C + (size_t)rr8 * ldc + col) = make_float2(acc[mi][ni][2], acc[mi][ni][3]);
        }
    }
}

// ---------------- tf32 GEMM NN: C[m,n] = sum_k A[m,k] * B[k,n] ----------------
__global__ void __launch_bounds__(256) mma_nn(
    const float* __restrict__ A, int lda, long long sA,
    const float* __restrict__ B, int ldb, long long sB,
    float* __restrict__ C, int ldc, long long sC,
    int M, int N, int K)
{
    extern __shared__ float smem[];
    float* As = smem;                 // 2 * ATILE
    float* Bs = smem + 2 * ATILE;     // 2 * BTILE_NN

    int z = blockIdx.z;
    A += (size_t)z * sA; B += (size_t)z * sB; C += (size_t)z * sC;
    int m0 = blockIdx.y * TBM;
    int n0 = blockIdx.x * TBN;

    int tid = threadIdx.x;
    // A loader: as in NT
    int larow[4], lacol[4];
    // B loader: tile TBK x TBN, 1024 float4, 4 per thread
    int lbrow[4], lbcol[4];
#pragma unroll
    for (int i = 0; i < 4; i++) {
        int idx = tid + i * 256;
        larow[i] = idx >> 3;
        lacol[i] = (idx & 7) * 4;
        lbrow[i] = idx >> 5;
        lbcol[i] = (idx & 31) * 4;
    }

    float4 rA[4], rB[4];
#pragma unroll
    for (int i = 0; i < 4; i++) {
        rA[i] = *(const float4*)(A + (size_t)(m0 + larow[i]) * lda + lacol[i]);
        rB[i] = *(const float4*)(B + (size_t)lbrow[i] * ldb + n0 + lbcol[i]);
    }
#pragma unroll
    for (int i = 0; i < 4; i++) {
        int ab = larow[i] * ASTR + lacol[i];
        *(uint4*)(As + ab) = make_uint4(f2tf(rA[i].x), f2tf(rA[i].y), f2tf(rA[i].z), f2tf(rA[i].w));
        int bb = lbrow[i] * BSTR_NN + lbcol[i];
        *(uint4*)(Bs + bb) = make_uint4(f2tf(rB[i].x), f2tf(rB[i].y), f2tf(rB[i].z), f2tf(rB[i].w));
    }
    __syncthreads();

    int lane = tid & 31, wid = tid >> 5;
    int wm = (wid & 1) * 64, wn = (wid >> 1) * 32;
    int g = lane >> 2, cc = lane & 3;

    float acc[4][4][4];
#pragma unroll
    for (int mi = 0; mi < 4; mi++)
#pragma unroll
        for (int ni = 0; ni < 4; ni++)
#pragma unroll
            for (int j = 0; j < 4; j++) acc[mi][ni][j] = 0.f;

    int buf = 0;
    for (int kt = TBK; kt <= K; kt += TBK) {
        bool has_next = kt < K;
        if (has_next) {
#pragma unroll
            for (int i = 0; i < 4; i++) {
                rA[i] = *(const float4*)(A + (size_t)(m0 + larow[i]) * lda + kt + lacol[i]);
                rB[i] = *(const float4*)(B + (size_t)(kt + lbrow[i]) * ldb + n0 + lbcol[i]);
            }
        }
        const uint32_t* ab = (const uint32_t*)(As + buf * ATILE);
        const uint32_t* bb = (const uint32_t*)(Bs + buf * BTILE_NN);
#pragma unroll
        for (int kk = 0; kk < TBK; kk += 8) {
            uint32_t af[4][4], bf[4][2];
#pragma unroll
            for (int mi = 0; mi < 4; mi++) {
                int r = wm + mi * 16 + g;
                af[mi][0] = ab[r * ASTR + kk + cc];
                af[mi][1] = ab[(r + 8) * ASTR + kk + cc];
                af[mi][2] = ab[r * ASTR + kk + cc + 4];
                af[mi][3] = ab[(r + 8) * ASTR + kk + cc + 4];
            }
#pragma unroll
            for (int ni = 0; ni < 4; ni++) {
                int n = wn + ni * 8 + g;
                bf[ni][0] = bb[(kk + cc) * BSTR_NN + n];
                bf[ni][1] = bb[(kk + cc + 4) * BSTR_NN + n];
            }
#pragma unroll
            for (int mi = 0; mi < 4; mi++)
#pragma unroll
                for (int ni = 0; ni < 4; ni++)
                    mma_tf32(acc[mi][ni], af[mi], bf[ni]);
        }
        if (has_next) {
            float* an = As + (buf ^ 1) * ATILE;
            float* bn = Bs + (buf ^ 1) * BTILE_NN;
#pragma unroll
            for (int i = 0; i < 4; i++) {
                int a = larow[i] * ASTR + lacol[i];
                *(uint4*)(an + a) = make_uint4(f2tf(rA[i].x), f2tf(rA[i].y), f2tf(rA[i].z), f2tf(rA[i].w));
                int b = lbrow[i] * BSTR_NN + lbcol[i];
                *(uint4*)(bn + b) = make_uint4(f2tf(rB[i].x), f2tf(rB[i].y), f2tf(rB[i].z), f2tf(rB[i].w));
            }
            __syncthreads();
            buf ^= 1;
        }
    }

#pragma unroll
    for (int mi = 0; mi < 4; mi++) {
        int r = m0 + wm + mi * 16 + g;
#pragma unroll
        for (int ni = 0; ni < 4; ni++) {
            int col = n0 + wn + ni * 8 + cc * 2;
            *(float2*)(C + (size_t)r * ldc + col) = make_float2(acc[mi][ni][0], acc[mi][ni][1]);
            *(float2*)(C + (size_t)(r + 8) * ldc + col) = make_float2(acc[mi][ni][2], acc[mi][ni][3]);
        }
    }
}

// ---------------- rmsnorm ----------------
__global__ void rmsnorm_kernel(const float* __restrict__ x, const float* __restrict__ w,
                               float* __restrict__ out, int ncols) {
    int row = blockIdx.x;
    const float* xr = x + (size_t)row * ncols;
    float ss = 0.f;
    for (int i = threadIdx.x; i < ncols; i += blockDim.x) {
        float v = xr[i];
        ss += v * v;
    }
    float tot = blk_sum(ss);
    float inv = rsqrtf(tot / (float)ncols + EPS);
    float* orow = out + (size_t)row * ncols;
    for (int i = threadIdx.x; i < ncols; i += blockDim.x)
        orow[i] = xr[i] * inv * w[i];
}

// ---------------- per-head q/k rmsnorm + rope ----------------
__global__ void qk_norm_rope(float* __restrict__ qkv,
                             const float* __restrict__ qw, const float* __restrict__ kw) {
    int t = blockIdx.x, h = blockIdx.y, which = blockIdx.z;
    float* base = qkv + (size_t)t * (3 * H) + (size_t)which * H + (size_t)h * HD;
    int d = threadIdx.x;
    float v = base[d];
    float tot = blk_sum(v * v);
    float inv = rsqrtf(tot / (float)HD + EPS);
    const float* w = which ? kw : qw;
    float nv = v * inv * w[d];
    __shared__ float buf[HD];
    buf[d] = nv;
    __syncthreads();
    if (d < HD / 2) {
        int i = d;
        double invf = pow(10000.0, -2.0 * (double)i / (double)HD);
        double ang = (double)t * invf;
        float c = (float)cos(ang), s = (float)sin(ang);
        float t1 = buf[2 * i], t2 = buf[2 * i + 1];
        base[2 * i]     = t1 * c - t2 * s;
        base[2 * i + 1] = t1 * s + t2 * c;
    }
}

// ---------------- causal softmax ----------------
__global__ void softmax_causal(float* __restrict__ S) {
    int t = blockIdx.x, h = blockIdx.y;
    float* row = S + ((size_t)h * T + t) * T;
    int n = t + 1;
    const float scale = 0.08838834764831845f;
    float mx = -3.4e38f;
    for (int j = threadIdx.x; j < n; j += blockDim.x)
        mx = fmaxf(mx, row[j] * scale);
    mx = blk_max(mx);
    float sum = 0.f;
    for (int j = threadIdx.x; j < n; j += blockDim.x) {
        float e = expf(row[j] * scale - mx);
        row[j] = e;
        sum += e;
    }
    sum = blk_sum(sum);
    float invs = 1.f / sum;
    for (int j = threadIdx.x; j < n; j += blockDim.x) row[j] *= invs;
    for (int j = n + (int)threadIdx.x; j < T; j += blockDim.x) row[j] = 0.f;
}

// ---------------- elementwise ----------------
__global__ void add2(const float* __restrict__ a, const float* __restrict__ b,
                     float* __restrict__ c, int n) {
    int i = blockIdx.x * blockDim.x + threadIdx.x;
    if (i < n) c[i] = a[i] + b[i];
}

__global__ void silu_mul(const float* __restrict__ gu, float* __restrict__ act) {
    int idx = blockIdx.x * blockDim.x + threadIdx.x;
    if (idx >= T * II) return;
    int t = idx / II, i = idx % II;
    float g = gu[(size_t)t * I2 + i];
    float u = gu[(size_t)t * I2 + II + i];
    act[(size_t)t * II + i] = (g / (1.f + expf(-g))) * u;
}

__global__ void final_out(const float* __restrict__ x2, const float* __restrict__ moe,
                          const float* __restrict__ topw, const float* __restrict__ shr,
                          float* __restrict__ out, int n) {
    int i = blockIdx.x * blockDim.x + threadIdx.x;
    if (i < n) {
        int t = i / H;
        out[i] = x2[i] + moe[i] * topw[t] + shr[i];
    }
}

// ---------------- routing ----------------
__global__ void gate_logits(const float* __restrict__ h2, const float* __restrict__ gw,
                            float* __restrict__ logits) {
    int t = blockIdx.x;
    __shared__ float xs[H];
    for (int i = threadIdx.x; i < H; i += blockDim.x) xs[i] = h2[(size_t)t * H + i];
    __syncthreads();
    int warp = threadIdx.x >> 5, lane = threadIdx.x & 31;
    for (int e = warp; e < NE; e += (blockDim.x >> 5)) {
        const float* w = gw + (size_t)e * H;
        float s = 0.f;
        for (int k = lane; k < H; k += 32) s += xs[k] * w[k];
#pragma unroll
        for (int o = 16; o; o >>= 1) s += __shfl_xor_sync(0xffffffffu, s, o);
        if (lane == 0) logits[(size_t)t * NE + e] = s;
    }
}

__global__ void route_topk(const float* __restrict__ logits, float* __restrict__ topw,
                           int* __restrict__ topi) {
    int t = blockIdx.x * blockDim.x + threadIdx.x;
    if (t >= T) return;
    float mx = -3.4e38f;
    int mi = 0;
#pragma unroll
    for (int e = 0; e < NE; e++) {
        float l = logits[(size_t)t * NE + e];
        if (l > mx) { mx = l; mi = e; }
    }
    float s = 0.f;
#pragma unroll
    for (int e = 0; e < NE; e++) s += expf(logits[(size_t)t * NE + e] - mx);
    topw[t] = 1.f / s;
    topi[t] = mi;
}

__global__ void zero_counts(int* c) {
    if (threadIdx.x < NE) c[threadIdx.x] = 0;
}

__global__ void build_route(const int* __restrict__ topi, int* __restrict__ counts,
                            int* __restrict__ rows) {
    int t = blockIdx.x * blockDim.x + threadIdx.x;
    if (t >= T) return;
    int e = topi[t];
    int p = atomicAdd(&counts[e], 1);
    rows[(size_t)e * T + p] = t;
}

// ---------------- host ----------------
#define SYM(p, s) do { void* _v; cudaGetSymbolAddress(&_v, s); p = (decltype(p))_v; } while (0)

extern "C" void kernel_launch(void* const* d_in, const int* in_sizes, int n_in,
                              void* d_out, int out_size) {
    const float* x      = (const float*)d_in[0];
    const float* ln1    = (const float*)d_in[1];
    const float* qkv_w  = (const float*)d_in[2];
    const float* qlnw   = (const float*)d_in[3];
    const float* klnw   = (const float*)d_in[4];
    const float* o_w    = (const float*)d_in[5];
    const float* ln2    = (const float*)d_in[6];
    const float* gate_w = (const float*)d_in[7];
    const float* egu    = (const float*)d_in[8];
    const float* edown  = (const float*)d_in[9];
    const float* sguw   = (const float*)d_in[10];
    const float* sdw    = (const float*)d_in[11];
    float* out = (float*)d_out;

    float *h, *qkv, *S, *attn, *tmp, *x2, *h2, *logits, *topw, *gu, *act, *moe, *sgu, *sact, *shr;
    int *topi, *counts, *rows;
    SYM(h, g_h); SYM(qkv, g_qkv); SYM(S, g_S); SYM(attn, g_attn); SYM(tmp, g_tmp);
    SYM(x2, g_x2); SYM(h2, g_h2); SYM(logits, g_logits); SYM(topw, g_topw);
    SYM(gu, g_gu); SYM(act, g_act); SYM(moe, g_moe); SYM(sgu, g_sgu); SYM(sact, g_sact);
    SYM(shr, g_shr); SYM(topi, g_topi); SYM(counts, g_counts); SYM(rows, g_rows);

    const int NT_SMEM = 4 * ATILE * 4;                       // 73728 B
    const int NN_SMEM = (2 * ATILE + 2 * BTILE_NN) * 4;      // 71680 B
    cudaFuncSetAttribute(mma_nt, cudaFuncAttributeMaxDynamicSharedMemorySize, NT_SMEM);
    cudaFuncSetAttribute(mma_nn, cudaFuncAttributeMaxDynamicSharedMemorySize, NN_SMEM);

    // 1. h = rmsnorm(x, ln1)
    rmsnorm_kernel<<<T, 256>>>(x, ln1, h, H);
    // 2. qkv = h @ qkv_w^T
    mma_nt<<<dim3(3 * H / TBN, T / TBM, 1), 256, NT_SMEM>>>(h, H, 0, qkv_w, H, 0, qkv, 3 * H, 0,
                                                            T, 3 * H, H, 0, 0);
    // 3. per-head q/k rmsnorm + rope
    qk_norm_rope<<<dim3(T, NH, 2), HD>>>(qkv, qlnw, klnw);
    // 4. S[h] = Q[h] @ K[h]^T
    mma_nt<<<dim3(T / TBN, T / TBM, NH), 256, NT_SMEM>>>(qkv, 3 * H, HD, qkv + H, 3 * H, HD,
                                                         S, T, (long long)T * T, T, T, HD, 0, 0);
    // 5. causal softmax
    softmax_causal<<<dim3(T, NH), 256>>>(S);
    // 6. attn[h] = P[h] @ V[h]
    mma_nn<<<dim3(HD / TBN, T / TBM, NH), 256, NN_SMEM>>>(S, T, (long long)T * T, qkv + 2 * H, 3 * H, HD,
                                                          attn, H, HD, T, HD, T);
    // 7. x2 = x + attn @ o_w^T
    mma_nt<<<dim3(H / TBN, T / TBM, 1), 256, NT_SMEM>>>(attn, H, 0, o_w, H, 0, tmp, H, 0, T, H, H, 0, 0);
    add2<<<(T * H + 255) / 256, 256>>>(x, tmp, x2, T * H);
    // 8. h2 = rmsnorm(x2, ln2)
    rmsnorm_kernel<<<T, 256>>>(x2, ln2, h2, H);
    // 9. routing
    gate_logits<<<T, 256>>>(h2, gate_w, logits);
    route_topk<<<(T + 255) / 256, 256>>>(logits, topw, topi);
    zero_counts<<<1, 32>>>(counts);
    build_route<<<(T + 255) / 256, 256>>>(topi, counts, rows);
    // 10. MoE (top-1, gathered)
    mma_nt<<<dim3(I2 / TBN, T / TBM, NE), 256, NT_SMEM>>>(h2, H, 0, egu, H, (long long)I2 * H,
                                                          gu, I2, 0, T, I2, H, rows, counts);
    silu_mul<<<(T * II + 255) / 256, 256>>>(gu, act);
    mma_nt<<<dim3(H / TBN, T / TBM, NE), 256, NT_SMEM>>>(act, II, 0, edown, II, (long long)H * II,
                                                         moe, H, 0, T, H, II, rows, counts);
    // 11. shared FFN
    mma_nt<<<dim3(I2 / TBN, T / TBM, 1), 256, NT_SMEM>>>(h2, H, 0, sguw, H, 0, sgu, I2, 0, T, I2, H, 0, 0);
    silu_mul<<<(T * II + 255) / 256, 256>>>(sgu, sact);
    mma_nt<<<dim3(H / TBN, T / TBM, 1), 256, NT_SMEM>>>(sact, II, 0, sdw, II, 0, shr, H, 0, T, H, II, 0, 0);
    // 12. out
    final_out<<<(T * H + 255) / 256, 256>>>(x2, moe, topw, shr, out, T * H);
}

// round 3
// speedup vs baseline: 2.8479x; 1.0324x over previous
#include <cuda_runtime.h>
#include <math.h>
#include <stdint.h>

#define T  2048
#define H  2048
#define NH 16
#define HD 128
#define NE 16
#define II 2048
#define I2 4096
#define EPS 1e-6f

#define TBM 128
#define TBN 128
#define TBK 32
#define ASTR 36                  // TBK + 4 pad
#define ATILE (TBM * ASTR)       // 4608 floats
#define BSTR_NN 136              // TBN + 8 pad
#define BTILE_NN (TBK * BSTR_NN) // 4352 floats

// ---------------- scratch ----------------
__device__ float g_h[(size_t)T * H];
__device__ float g_qkv[(size_t)T * 3 * H];
__device__ float g_S[(size_t)NH * T * T];
__device__ float g_attn[(size_t)T * H];
__device__ float g_x2[(size_t)T * H];
__device__ float g_h2[(size_t)T * H];
__device__ float g_logits[(size_t)T * NE];
__device__ float g_topw[T];
__device__ int   g_topi[T];
__device__ int   g_counts[NE];
__device__ int   g_rows[(size_t)NE * T];
__device__ float g_gu[(size_t)T * I2];
__device__ float g_act[(size_t)T * II];
__device__ float g_moe[(size_t)T * H];
__device__ float g_sgu[(size_t)T * I2];
__device__ float g_sact[(size_t)T * II];

// ---------------- helpers ----------------
__device__ __forceinline__ uint32_t f2tf(float x) {
    uint32_t u;
    asm("cvt.rna.tf32.f32 %0, %1;" : "=r"(u) : "f"(x));
    return u;
}

__device__ __forceinline__ void mma_tf32(float c[4], const uint32_t a[4], const uint32_t b[2]) {
    asm volatile("mma.sync.aligned.m16n8k8.row.col.f32.tf32.tf32.f32 "
                 "{%0,%1,%2,%3}, {%4,%5,%6,%7}, {%8,%9}, {%0,%1,%2,%3};"
                 : "+f"(c[0]), "+f"(c[1]), "+f"(c[2]), "+f"(c[3])
                 : "r"(a[0]), "r"(a[1]), "r"(a[2]), "r"(a[3]), "r"(b[0]), "r"(b[1]));
}

__device__ __forceinline__ float blk_sum(float v) {
    __shared__ float sh[33];
    __syncthreads();
    int lane = threadIdx.x & 31, w = threadIdx.x >> 5;
#pragma unroll
    for (int o = 16; o; o >>= 1) v += __shfl_xor_sync(0xffffffffu, v, o);
    if (lane == 0) sh[w] = v;
    __syncthreads();
    if (threadIdx.x < 32) {
        int nw = (blockDim.x + 31) >> 5;
        float r = (threadIdx.x < nw) ? sh[threadIdx.x] : 0.f;
#pragma unroll
        for (int o = 16; o; o >>= 1) r += __shfl_xor_sync(0xffffffffu, r, o);
        if (threadIdx.x == 0) sh[32] = r;
    }
    __syncthreads();
    return sh[32];
}

__device__ __forceinline__ float blk_max(float v) {
    __shared__ float sh[33];
    __syncthreads();
    int lane = threadIdx.x & 31, w = threadIdx.x >> 5;
#pragma unroll
    for (int o = 16; o; o >>= 1) v = fmaxf(v, __shfl_xor_sync(0xffffffffu, v, o));
    if (lane == 0) sh[w] = v;
    __syncthreads();
    if (threadIdx.x < 32) {
        int nw = (blockDim.x + 31) >> 5;
        float r = (threadIdx.x < nw) ? sh[threadIdx.x] : -3.4e38f;
#pragma unroll
        for (int o = 16; o; o >>= 1) r = fmaxf(r, __shfl_xor_sync(0xffffffffu, r, o));
        if (threadIdx.x == 0) sh[32] = r;
    }
    __syncthreads();
    return sh[32];
}

// ---------------- tf32 GEMM NT (512 threads, 16 warps, warp tile 32x32) ----------------
// C[m,n] = sum_k A[m,k]*B[n,k] (+addA) (+addS*scaleVec[m]); optional row-gather; causal skip
__global__ void __launch_bounds__(512) mma_nt(
    const float* __restrict__ A, int lda, long long sA,
    const float* __restrict__ B, int ldb, long long sB,
    float* __restrict__ C, int ldc, long long sC,
    int M, int N, int K,
    const int* __restrict__ rowsAll, const int* __restrict__ cntAll,
    int causal,
    const float* __restrict__ addA,
    const float* __restrict__ addS, const float* __restrict__ scaleVec)
{
    extern __shared__ float smem[];
    float* As = smem;
    float* Bs = smem + 2 * ATILE;
    __shared__ int rid[TBM];

    int z = blockIdx.z;
    A += (size_t)z * sA; B += (size_t)z * sB; C += (size_t)z * sC;
    const int* rows = rowsAll ? rowsAll + (size_t)z * M : 0;
    int Mv = cntAll ? cntAll[z] : M;
    int m0 = blockIdx.y * TBM;
    if (m0 >= Mv) return;
    int n0 = blockIdx.x * TBN;
    if (causal && n0 > m0) return;

    int tid = threadIdx.x;
    if (tid < TBM) {
        int gm = m0 + tid;
        rid[tid] = rows ? (gm < Mv ? rows[gm] : -1) : gm;
    }
    __syncthreads();

    // loaders: 1024 float4 per tile / 512 threads = 2 each
    int lrow[2], lcol[2], ra[2];
#pragma unroll
    for (int i = 0; i < 2; i++) {
        int idx = tid + i * 512;
        lrow[i] = idx >> 3;
        lcol[i] = (idx & 7) * 4;
        ra[i] = rid[lrow[i]];
    }

    float4 rA[2], rB[2];
    const float4 z4 = make_float4(0.f, 0.f, 0.f, 0.f);
#pragma unroll
    for (int i = 0; i < 2; i++) {
        rA[i] = (ra[i] >= 0) ? *(const float4*)(A + (size_t)ra[i] * lda + lcol[i]) : z4;
        rB[i] = *(const float4*)(B + (size_t)(n0 + lrow[i]) * ldb + lcol[i]);
    }
#pragma unroll
    for (int i = 0; i < 2; i++) {
        int base = lrow[i] * ASTR + lcol[i];
        *(uint4*)(As + base) = make_uint4(f2tf(rA[i].x), f2tf(rA[i].y), f2tf(rA[i].z), f2tf(rA[i].w));
        *(uint4*)(Bs + base) = make_uint4(f2tf(rB[i].x), f2tf(rB[i].y), f2tf(rB[i].z), f2tf(rB[i].w));
    }
    __syncthreads();

    int lane = tid & 31, wid = tid >> 5;
    int wm = (wid & 3) * 32, wn = (wid >> 2) * 32;
    int g = lane >> 2, cc = lane & 3;

    float acc[2][4][4];
#pragma unroll
    for (int mi = 0; mi < 2; mi++)
#pragma unroll
        for (int ni = 0; ni < 4; ni++)
#pragma unroll
            for (int j = 0; j < 4; j++) acc[mi][ni][j] = 0.f;

    int buf = 0;
    for (int kt = TBK; kt <= K; kt += TBK) {
        bool has_next = kt < K;
        if (has_next) {
#pragma unroll
            for (int i = 0; i < 2; i++) {
                rA[i] = (ra[i] >= 0) ? *(const float4*)(A + (size_t)ra[i] * lda + kt + lcol[i]) : z4;
                rB[i] = *(const float4*)(B + (size_t)(n0 + lrow[i]) * ldb + kt + lcol[i]);
            }
        }
        const uint32_t* ab = (const uint32_t*)(As + buf * ATILE);
        const uint32_t* bb = (const uint32_t*)(Bs + buf * ATILE);
#pragma unroll
        for (int kk = 0; kk < TBK; kk += 8) {
            uint32_t af[2][4], bf[4][2];
#pragma unroll
            for (int mi = 0; mi < 2; mi++) {
                int r = wm + mi * 16 + g;
                af[mi][0] = ab[r * ASTR + kk + cc];
                af[mi][1] = ab[(r + 8) * ASTR + kk + cc];
                af[mi][2] = ab[r * ASTR + kk + cc + 4];
                af[mi][3] = ab[(r + 8) * ASTR + kk + cc + 4];
            }
#pragma unroll
            for (int ni = 0; ni < 4; ni++) {
                int n = wn + ni * 8 + g;
                bf[ni][0] = bb[n * ASTR + kk + cc];
                bf[ni][1] = bb[n * ASTR + kk + cc + 4];
            }
#pragma unroll
            for (int mi = 0; mi < 2; mi++)
#pragma unroll
                for (int ni = 0; ni < 4; ni++)
                    mma_tf32(acc[mi][ni], af[mi], bf[ni]);
        }
        if (has_next) {
            float* an = As + (buf ^ 1) * ATILE;
            float* bn = Bs + (buf ^ 1) * ATILE;
#pragma unroll
            for (int i = 0; i < 2; i++) {
                int base = lrow[i] * ASTR + lcol[i];
                *(uint4*)(an + base) = make_uint4(f2tf(rA[i].x), f2tf(rA[i].y), f2tf(rA[i].z), f2tf(rA[i].w));
                *(uint4*)(bn + base) = make_uint4(f2tf(rB[i].x), f2tf(rB[i].y), f2tf(rB[i].z), f2tf(rB[i].w));
            }
            __syncthreads();
            buf ^= 1;
        }
    }

#pragma unroll
    for (int mi = 0; mi < 2; mi++) {
        int r0 = wm + mi * 16 + g;
        int rr[2] = { rid[r0], rid[r0 + 8] };
#pragma unroll
        for (int half = 0; half < 2; half++) {
            int r = rr[half];
            if (r < 0) continue;
#pragma unroll
            for (int ni = 0; ni < 4; ni++) {
                int col = n0 + wn + ni * 8 + cc * 2;
                float2 v = make_float2(acc[mi][ni][half * 2], acc[mi][ni][half * 2 + 1]);
                if (addA) {
                    float2 a = *(const float2*)(addA + (size_t)r * ldc + col);
                    v.x += a.x; v.y += a.y;
                }
                if (addS) {
                    float w = scaleVec[r];
                    float2 s = *(const float2*)(addS + (size_t)r * ldc + col);
                    v.x += s.x * w; v.y += s.y * w;
                }
                *(float2*)(C + (size_t)r * ldc + col) = v;
            }
        }
    }
}

// ---------------- tf32 GEMM NN (512 threads): C = A @ B, optional causal K-cap ----------------
__global__ void __launch_bounds__(512) mma_nn(
    const float* __restrict__ A, int lda, long long sA,
    const float* __restrict__ B, int ldb, long long sB,
    float* __restrict__ C, int ldc, long long sC,
    int M, int N, int K, int kcap)
{
    extern __shared__ float smem[];
    float* As = smem;
    float* Bs = smem + 2 * ATILE;

    int z = blockIdx.z;
    A += (size_t)z * sA; B += (size_t)z * sB; C += (size_t)z * sC;
    int m0 = blockIdx.y * TBM;
    int n0 = blockIdx.x * TBN;
    int Keff = kcap ? min(K, m0 + TBM) : K;

    int tid = threadIdx.x;
    int larow[2], lacol[2], lbrow[2], lbcol[2];
#pragma unroll
    for (int i = 0; i < 2; i++) {
        int idx = tid + i * 512;
        larow[i] = idx >> 3;
        lacol[i] = (idx & 7) * 4;
        lbrow[i] = idx >> 5;
        lbcol[i] = (idx & 31) * 4;
    }

    float4 rA[2], rB[2];
#pragma unroll
    for (int i = 0; i < 2; i++) {
        rA[i] = *(const float4*)(A + (size_t)(m0 + larow[i]) * lda + lacol[i]);
        rB[i] = *(const float4*)(B + (size_t)lbrow[i] * ldb + n0 + lbcol[i]);
    }
#pragma unroll
    for (int i = 0; i < 2; i++) {
        int a = larow[i] * ASTR + lacol[i];
        *(uint4*)(As + a) = make_uint4(f2tf(rA[i].x), f2tf(rA[i].y), f2tf(rA[i].z), f2tf(rA[i].w));
        int b = lbrow[i] * BSTR_NN + lbcol[i];
        *(uint4*)(Bs + b) = make_uint4(f2tf(rB[i].x), f2tf(rB[i].y), f2tf(rB[i].z), f2tf(rB[i].w));
    }
    __syncthreads();

    int lane = tid & 31, wid = tid >> 5;
    int wm = (wid & 3) * 32, wn = (wid >> 2) * 32;
    int g = lane >> 2, cc = lane & 3;

    float acc[2][4][4];
#pragma unroll
    for (int mi = 0; mi < 2; mi++)
#pragma unroll
        for (int ni = 0; ni < 4; ni++)
#pragma unroll
            for (int j = 0; j < 4; j++) acc[mi][ni][j] = 0.f;

    int buf = 0;
    for (int kt = TBK; kt <= Keff; kt += TBK) {
        bool has_next = kt < Keff;
        if (has_next) {
#pragma unroll
            for (int i = 0; i < 2; i++) {
                rA[i] = *(const float4*)(A + (size_t)(m0 + larow[i]) * lda + kt + lacol[i]);
                rB[i] = *(const float4*)(B + (size_t)(kt + lbrow[i]) * ldb + n0 + lbcol[i]);
            }
        }
        const uint32_t* ab = (const uint32_t*)(As + buf * ATILE);
        const uint32_t* bb = (const uint32_t*)(Bs + buf * BTILE_NN);
#pragma unroll
        for (int kk = 0; kk < TBK; kk += 8) {
            uint32_t af[2][4], bf[4][2];
#pragma unroll
            for (int mi = 0; mi < 2; mi++) {
                int r = wm + mi * 16 + g;
                af[mi][0] = ab[r * ASTR + kk + cc];
                af[mi][1] = ab[(r + 8) * ASTR + kk + cc];
                af[mi][2] = ab[r * ASTR + kk + cc + 4];
                af[mi][3] = ab[(r + 8) * ASTR + kk + cc + 4];
            }
#pragma unroll
            for (int ni = 0; ni < 4; ni++) {
                int n = wn + ni * 8 + g;
                bf[ni][0] = bb[(kk + cc) * BSTR_NN + n];
                bf[ni][1] = bb[(kk + cc + 4) * BSTR_NN + n];
            }
#pragma unroll
            for (int mi = 0; mi < 2; mi++)
#pragma unroll
                for (int ni = 0; ni < 4; ni++)
                    mma_tf32(acc[mi][ni], af[mi], bf[ni]);
        }
        if (has_next) {
            float* an = As + (buf ^ 1) * ATILE;
            float* bn = Bs + (buf ^ 1) * BTILE_NN;
#pragma unroll
            for (int i = 0; i < 2; i++) {
                int a = larow[i] * ASTR + lacol[i];
                *(uint4*)(an + a) = make_uint4(f2tf(rA[i].x), f2tf(rA[i].y), f2tf(rA[i].z), f2tf(rA[i].w));
                int b = lbrow[i] * BSTR_NN + lbcol[i];
                *(uint4*)(bn + b) = make_uint4(f2tf(rB[i].x), f2tf(rB[i].y), f2tf(rB[i].z), f2tf(rB[i].w));
            }
            __syncthreads();
            buf ^= 1;
        }
    }

#pragma unroll
    for (int mi = 0; mi < 2; mi++) {
        int r = m0 + wm + mi * 16 + g;
#pragma unroll
        for (int ni = 0; ni < 4; ni++) {
            int col = n0 + wn + ni * 8 + cc * 2;
            *(float2*)(C + (size_t)r * ldc + col) = make_float2(acc[mi][ni][0], acc[mi][ni][1]);
            *(float2*)(C + (size_t)(r + 8) * ldc + col) = make_float2(acc[mi][ni][2], acc[mi][ni][3]);
        }
    }
}

// ---------------- rmsnorm ----------------
__global__ void rmsnorm_kernel(const float* __restrict__ x, const float* __restrict__ w,
                               float* __restrict__ out, int ncols) {
    int row = blockIdx.x;
    const float* xr = x + (size_t)row * ncols;
    float ss = 0.f;
    for (int i = threadIdx.x; i < ncols; i += blockDim.x) {
        float v = xr[i];
        ss += v * v;
    }
    float tot = blk_sum(ss);
    float inv = rsqrtf(tot / (float)ncols + EPS);
    float* orow = out + (size_t)row * ncols;
    for (int i = threadIdx.x; i < ncols; i += blockDim.x)
        orow[i] = xr[i] * inv * w[i];
}

// ---------------- per-head q/k rmsnorm + rope ----------------
__global__ void qk_norm_rope(float* __restrict__ qkv,
                             const float* __restrict__ qw, const float* __restrict__ kw) {
    int t = blockIdx.x, h = blockIdx.y, which = blockIdx.z;
    float* base = qkv + (size_t)t * (3 * H) + (size_t)which * H + (size_t)h * HD;
    int d = threadIdx.x;
    float v = base[d];
    float tot = blk_sum(v * v);
    float inv = rsqrtf(tot / (float)HD + EPS);
    const float* w = which ? kw : qw;
    float nv = v * inv * w[d];
    __shared__ float buf[HD];
    buf[d] = nv;
    __syncthreads();
    if (d < HD / 2) {
        int i = d;
        double invf = pow(10000.0, -2.0 * (double)i / (double)HD);
        double ang = (double)t * invf;
        float c = (float)cos(ang), s = (float)sin(ang);
        float t1 = buf[2 * i], t2 = buf[2 * i + 1];
        base[2 * i]     = t1 * c - t2 * s;
        base[2 * i + 1] = t1 * s + t2 * c;
    }
}

// ---------------- causal softmax (zero-fill only to diagonal-block end) ----------------
__global__ void softmax_causal(float* __restrict__ S) {
    int t = blockIdx.x, h = blockIdx.y;
    float* row = S + ((size_t)h * T + t) * T;
    int n = t + 1;
    int fill_end = min(T, ((t >> 7) + 1) << 7);
    const float scale = 0.08838834764831845f;
    float mx = -3.4e38f;
    for (int j = threadIdx.x; j < n; j += blockDim.x)
        mx = fmaxf(mx, row[j] * scale);
    mx = blk_max(mx);
    float sum = 0.f;
    for (int j = threadIdx.x; j < n; j += blockDim.x) {
        float e = expf(row[j] * scale - mx);
        row[j] = e;
        sum += e;
    }
    sum = blk_sum(sum);
    float invs = 1.f / sum;
    for (int j = threadIdx.x; j < n; j += blockDim.x) row[j] *= invs;
    for (int j = n + (int)threadIdx.x; j < fill_end; j += blockDim.x) row[j] = 0.f;
}

// ---------------- elementwise ----------------
__global__ void silu_mul(const float* __restrict__ gu, float* __restrict__ act) {
    int idx = blockIdx.x * blockDim.x + threadIdx.x;
    if (idx >= T * II) return;
    int t = idx / II, i = idx % II;
    float g = gu[(size_t)t * I2 + i];
    float u = gu[(size_t)t * I2 + II + i];
    act[(size_t)t * II + i] = (g / (1.f + expf(-g))) * u;
}

// ---------------- routing ----------------
__global__ void gate_logits(const float* __restrict__ h2, const float* __restrict__ gw,
                            float* __restrict__ logits) {
    int t = blockIdx.x;
    __shared__ float xs[H];
    for (int i = threadIdx.x; i < H; i += blockDim.x) xs[i] = h2[(size_t)t * H + i];
    __syncthreads();
    int warp = threadIdx.x >> 5, lane = threadIdx.x & 31;
    for (int e = warp; e < NE; e += (blockDim.x >> 5)) {
        const float* w = gw + (size_t)e * H;
        float s = 0.f;
        for (int k = lane; k < H; k += 32) s += xs[k] * w[k];
#pragma unroll
        for (int o = 16; o; o >>= 1) s += __shfl_xor_sync(0xffffffffu, s, o);
        if (lane == 0) logits[(size_t)t * NE + e] = s;
    }
}

__global__ void route_topk(const float* __restrict__ logits, float* __restrict__ topw,
                           int* __restrict__ topi) {
    int t = blockIdx.x * blockDim.x + threadIdx.x;
    if (t >= T) return;
    float mx = -3.4e38f;
    int mi = 0;
#pragma unroll
    for (int e = 0; e < NE; e++) {
        float l = logits[(size_t)t * NE + e];
        if (l > mx) { mx = l; mi = e; }
    }
    float s = 0.f;
#pragma unroll
    for (int e = 0; e < NE; e++) s += expf(logits[(size_t)t * NE + e] - mx);
    topw[t] = 1.f / s;
    topi[t] = mi;
}

__global__ void zero_counts(int* c) {
    if (threadIdx.x < NE) c[threadIdx.x] = 0;
}

__global__ void build_route(const int* __restrict__ topi, int* __restrict__ counts,
                            int* __restrict__ rows) {
    int t = blockIdx.x * blockDim.x + threadIdx.x;
    if (t >= T) return;
    int e = topi[t];
    int p = atomicAdd(&counts[e], 1);
    rows[(size_t)e * T + p] = t;
}

// ---------------- host ----------------
#define SYM(p, s) do { void* _v; cudaGetSymbolAddress(&_v, s); p = (decltype(p))_v; } while (0)

extern "C" void kernel_launch(void* const* d_in, const int* in_sizes, int n_in,
                              void* d_out, int out_size) {
    const float* x      = (const float*)d_in[0];
    const float* ln1    = (const float*)d_in[1];
    const float* qkv_w  = (const float*)d_in[2];
    const float* qlnw   = (const float*)d_in[3];
    const float* klnw   = (const float*)d_in[4];
    const float* o_w    = (const float*)d_in[5];
    const float* ln2    = (const float*)d_in[6];
    const float* gate_w = (const float*)d_in[7];
    const float* egu    = (const float*)d_in[8];
    const float* edown  = (const float*)d_in[9];
    const float* sguw   = (const float*)d_in[10];
    const float* sdw    = (const float*)d_in[11];
    float* out = (float*)d_out;

    float *h, *qkv, *S, *attn, *x2, *h2, *logits, *topw, *gu, *act, *moe, *sgu, *sact;
    int *topi, *counts, *rows;
    SYM(h, g_h); SYM(qkv, g_qkv); SYM(S, g_S); SYM(attn, g_attn);
    SYM(x2, g_x2); SYM(h2, g_h2); SYM(logits, g_logits); SYM(topw, g_topw);
    SYM(gu, g_gu); SYM(act, g_act); SYM(moe, g_moe); SYM(sgu, g_sgu); SYM(sact, g_sact);
    SYM(topi, g_topi); SYM(counts, g_counts); SYM(rows, g_rows);

    const int NT_SMEM = 4 * ATILE * 4;
    const int NN_SMEM = (2 * ATILE + 2 * BTILE_NN) * 4;
    cudaFuncSetAttribute(mma_nt, cudaFuncAttributeMaxDynamicSharedMemorySize, NT_SMEM);
    cudaFuncSetAttribute(mma_nn, cudaFuncAttributeMaxDynamicSharedMemorySize, NN_SMEM);

    // 1. h = rmsnorm(x, ln1)
    rmsnorm_kernel<<<T, 256>>>(x, ln1, h, H);
    // 2. qkv = h @ qkv_w^T
    mma_nt<<<dim3(3 * H / TBN, T / TBM, 1), 512, NT_SMEM>>>(h, H, 0, qkv_w, H, 0, qkv, 3 * H, 0,
                                                            T, 3 * H, H, 0, 0, 0, 0, 0, 0);
    // 3. q/k rmsnorm + rope
    qk_norm_rope<<<dim3(T, NH, 2), HD>>>(qkv, qlnw, klnw);
    // 4. S[h] = Q[h] @ K[h]^T (causal block skip)
    mma_nt<<<dim3(T / TBN, T / TBM, NH), 512, NT_SMEM>>>(qkv, 3 * H, HD, qkv + H, 3 * H, HD,
                                                         S, T, (long long)T * T, T, T, HD,
                                                         0, 0, 1, 0, 0, 0);
    // 5. causal softmax
    softmax_causal<<<dim3(T, NH), 256>>>(S);
    // 6. attn[h] = P[h] @ V[h]  (K capped at diagonal block)
    mma_nn<<<dim3(HD / TBN, T / TBM, NH), 512, NN_SMEM>>>(S, T, (long long)T * T, qkv + 2 * H, 3 * H, HD,
                                                          attn, H, HD, T, HD, T, 1);
    // 7. x2 = x + attn @ o_w^T (fused residual)
    mma_nt<<<dim3(H / TBN, T / TBM, 1), 512, NT_SMEM>>>(attn, H, 0, o_w, H, 0, x2, H, 0,
                                                        T, H, H, 0, 0, 0, x, 0, 0);
    // 8. h2 = rmsnorm(x2, ln2)
    rmsnorm_kernel<<<T, 256>>>(x2, ln2, h2, H);
    // 9. routing
    gate_logits<<<T, 256>>>(h2, gate_w, logits);
    route_topk<<<(T + 255) / 256, 256>>>(logits, topw, topi);
    zero_counts<<<1, 32>>>(counts);
    build_route<<<(T + 255) / 256, 256>>>(topi, counts, rows);
    // 10. MoE (top-1, gathered)
    mma_nt<<<dim3(I2 / TBN, T / TBM, NE), 512, NT_SMEM>>>(h2, H, 0, egu, H, (long long)I2 * H,
                                                          gu, I2, 0, T, I2, H, rows, counts, 0, 0, 0, 0);
    silu_mul<<<(T * II + 255) / 256, 256>>>(gu, act);
    mma_nt<<<dim3(H / TBN, T / TBM, NE), 512, NT_SMEM>>>(act, II, 0, edown, II, (long long)H * II,
                                                         moe, H, 0, T, H, II, rows, counts, 0, 0, 0, 0);
    // 11. shared FFN
    mma_nt<<<dim3(I2 / TBN, T / TBM, 1), 512, NT_SMEM>>>(h2, H, 0, sguw, H, 0, sgu, I2, 0,
                                                         T, I2, H, 0, 0, 0, 0, 0, 0);
    silu_mul<<<(T * II + 255) / 256, 256>>>(sgu, sact);
    // 12. out = x2 + topw*moe + sact @ sdw^T (fully fused final)
    mma_nt<<<dim3(H / TBN, T / TBM, 1), 512, NT_SMEM>>>(sact, II, 0, sdw, II, 0, out, H, 0,
                                                        T, H, II, 0, 0, 0, x2, moe, topw);
}

// round 4
// speedup vs baseline: 3.0348x; 1.0656x over previous
#include <cuda_runtime.h>
#include <math.h>
#include <stdint.h>

#define T  2048
#define H  2048
#define NH 16
#define HD 128
#define NE 16
#define II 2048
#define I2 4096
#define EPS 1e-6f

#define TBM 128
#define TBN 128
#define TBK 32
// permuted-layout constants: KB=4 k-blocks of 8; kblk stride 33 groups, m/n-blk stride 133 groups
#define KBLK_STR 33
#define MBLK_STR 133
#define APERM 4256   // floats per stage (A: 8 mblk * 133 * 4w ; B: 16 nblk * 133 * 2w)

// ---------------- scratch ----------------
__device__ float g_h[(size_t)T * H];
__device__ float g_qkv[(size_t)T * 3 * H];
__device__ float g_S[(size_t)NH * T * T];
__device__ float g_attn[(size_t)T * H];
__device__ float g_x2[(size_t)T * H];
__device__ float g_h2[(size_t)T * H];
__device__ float g_logits[(size_t)T * NE];
__device__ float g_topw[T];
__device__ int   g_topi[T];
__device__ int   g_counts[NE];
__device__ int   g_rows[(size_t)NE * T];
__device__ float g_gu[(size_t)T * I2];
__device__ float g_act[(size_t)T * II];
__device__ float g_moe[(size_t)T * H];
__device__ float g_sgu[(size_t)T * I2];
__device__ float g_sact[(size_t)T * II];

// ---------------- helpers ----------------
__device__ __forceinline__ uint32_t f2tf(float x) {
    uint32_t u;
    asm("cvt.rna.tf32.f32 %0, %1;" : "=r"(u) : "f"(x));
    return u;
}

__device__ __forceinline__ void mma_tf32(float c[4], uint4 a, uint2 b) {
    asm volatile("mma.sync.aligned.m16n8k8.row.col.f32.tf32.tf32.f32 "
                 "{%0,%1,%2,%3}, {%4,%5,%6,%7}, {%8,%9}, {%0,%1,%2,%3};"
                 : "+f"(c[0]), "+f"(c[1]), "+f"(c[2]), "+f"(c[3])
                 : "r"(a.x), "r"(a.y), "r"(a.z), "r"(a.w), "r"(b.x), "r"(b.y));
}

__device__ __forceinline__ float blk_sum(float v) {
    __shared__ float sh[33];
    __syncthreads();
    int lane = threadIdx.x & 31, w = threadIdx.x >> 5;
#pragma unroll
    for (int o = 16; o; o >>= 1) v += __shfl_xor_sync(0xffffffffu, v, o);
    if (lane == 0) sh[w] = v;
    __syncthreads();
    if (threadIdx.x < 32) {
        int nw = (blockDim.x + 31) >> 5;
        float r = (threadIdx.x < nw) ? sh[threadIdx.x] : 0.f;
#pragma unroll
        for (int o = 16; o; o >>= 1) r += __shfl_xor_sync(0xffffffffu, r, o);
        if (threadIdx.x == 0) sh[32] = r;
    }
    __syncthreads();
    return sh[32];
}

__device__ __forceinline__ float blk_max(float v) {
    __shared__ float sh[33];
    __syncthreads();
    int lane = threadIdx.x & 31, w = threadIdx.x >> 5;
#pragma unroll
    for (int o = 16; o; o >>= 1) v = fmaxf(v, __shfl_xor_sync(0xffffffffu, v, o));
    if (lane == 0) sh[w] = v;
    __syncthreads();
    if (threadIdx.x < 32) {
        int nw = (blockDim.x + 31) >> 5;
        float r = (threadIdx.x < nw) ? sh[threadIdx.x] : -3.4e38f;
#pragma unroll
        for (int o = 16; o; o >>= 1) r = fmaxf(r, __shfl_xor_sync(0xffffffffu, r, o));
        if (threadIdx.x == 0) sh[32] = r;
    }
    __syncthreads();
    return sh[32];
}

// store 4 consecutive-k tf32 values of one A-row (row-within-tile r, k0 multiple of 4)
__device__ __forceinline__ int a_perm_base(int r, int k0) {
    int mblk = r >> 4, g = r & 7, half = (r >> 3) & 1;
    int kblk = k0 >> 3, k4 = (k0 >> 2) & 1;
    return (mblk * MBLK_STR + kblk * KBLK_STR + g * 4) * 4 + (half + 2 * k4);
}
__device__ __forceinline__ int b_perm_base(int r, int k0) {
    int nblk = r >> 3, g = r & 7;
    int kblk = k0 >> 3, k4 = (k0 >> 2) & 1;
    return (nblk * MBLK_STR + kblk * KBLK_STR + g * 4) * 2 + k4;
}
__device__ __forceinline__ void a_store4(float* As, int base, float4 v) {
    As[base]      = __uint_as_float(f2tf(v.x));
    As[base + 4]  = __uint_as_float(f2tf(v.y));
    As[base + 8]  = __uint_as_float(f2tf(v.z));
    As[base + 12] = __uint_as_float(f2tf(v.w));
}
__device__ __forceinline__ void b_store4(float* Bs, int base, float4 v) {
    Bs[base]     = __uint_as_float(f2tf(v.x));
    Bs[base + 2] = __uint_as_float(f2tf(v.y));
    Bs[base + 4] = __uint_as_float(f2tf(v.z));
    Bs[base + 6] = __uint_as_float(f2tf(v.w));
}

// ---------------- tf32 GEMM NT (512 thr), permuted smem, vectorized frag loads ----
__global__ void __launch_bounds__(512) mma_nt(
    const float* __restrict__ A, int lda, long long sA,
    const float* __restrict__ B, int ldb, long long sB,
    float* __restrict__ C, int ldc, long long sC,
    int M, int N, int K,
    const int* __restrict__ rowsAll, const int* __restrict__ cntAll,
    int causal,
    const float* __restrict__ addA,
    const float* __restrict__ addS, const float* __restrict__ scaleVec)
{
    extern __shared__ float smem[];
    float* As = smem;                  // 2 * APERM
    float* Bs = smem + 2 * APERM;      // 2 * APERM
    __shared__ int rid[TBM];

    int z = blockIdx.z;
    A += (size_t)z * sA; B += (size_t)z * sB; C += (size_t)z * sC;
    const int* rows = rowsAll ? rowsAll + (size_t)z * M : 0;
    int Mv = cntAll ? cntAll[z] : M;
    int m0 = blockIdx.y * TBM;
    if (m0 >= Mv) return;
    int n0 = blockIdx.x * TBN;
    if (causal && n0 > m0) return;

    int tid = threadIdx.x;
    if (tid < TBM) {
        int gm = m0 + tid;
        rid[tid] = rows ? (gm < Mv ? rows[gm] : -1) : gm;
    }
    __syncthreads();

    int lrow[2], lcol[2], ra[2], abase[2], bbase[2];
#pragma unroll
    for (int i = 0; i < 2; i++) {
        int idx = tid + i * 512;
        lrow[i] = idx >> 3;
        lcol[i] = (idx & 7) * 4;
        ra[i] = rid[lrow[i]];
        abase[i] = a_perm_base(lrow[i], lcol[i]);
        bbase[i] = b_perm_base(lrow[i], lcol[i]);
    }

    float4 rA[2], rB[2];
    const float4 z4 = make_float4(0.f, 0.f, 0.f, 0.f);
#pragma unroll
    for (int i = 0; i < 2; i++) {
        rA[i] = (ra[i] >= 0) ? *(const float4*)(A + (size_t)ra[i] * lda + lcol[i]) : z4;
        rB[i] = *(const float4*)(B + (size_t)(n0 + lrow[i]) * ldb + lcol[i]);
    }
#pragma unroll
    for (int i = 0; i < 2; i++) {
        a_store4(As, abase[i], rA[i]);
        b_store4(Bs, bbase[i], rB[i]);
    }
    __syncthreads();

    int lane = tid & 31, wid = tid >> 5;
    int wmblk = (wid & 3) * 2;     // A m-block base (each 16 rows)
    int wnblk = (wid >> 2) * 4;    // B n-block base (each 8 cols)
    int g = lane >> 2, cc = lane & 3;
    int fragoff = g * 4 + cc;

    float acc[2][4][4];
#pragma unroll
    for (int mi = 0; mi < 2; mi++)
#pragma unroll
        for (int ni = 0; ni < 4; ni++)
#pragma unroll
            for (int j = 0; j < 4; j++) acc[mi][ni][j] = 0.f;

    int buf = 0;
    for (int kt = TBK; kt <= K; kt += TBK) {
        bool has_next = kt < K;
        if (has_next) {
#pragma unroll
            for (int i = 0; i < 2; i++) {
                rA[i] = (ra[i] >= 0) ? *(const float4*)(A + (size_t)ra[i] * lda + kt + lcol[i]) : z4;
                rB[i] = *(const float4*)(B + (size_t)(n0 + lrow[i]) * ldb + kt + lcol[i]);
            }
        }
        const float* Ab = As + buf * APERM;
        const float* Bb = Bs + buf * APERM;
#pragma unroll
        for (int kblk = 0; kblk < 4; kblk++) {
            uint4 af[2];
            uint2 bf[4];
#pragma unroll
            for (int mi = 0; mi < 2; mi++)
                af[mi] = *(const uint4*)(Ab + ((wmblk + mi) * MBLK_STR + kblk * KBLK_STR + fragoff) * 4);
#pragma unroll
            for (int ni = 0; ni < 4; ni++)
                bf[ni] = *(const uint2*)(Bb + ((wnblk + ni) * MBLK_STR + kblk * KBLK_STR + fragoff) * 2);
#pragma unroll
            for (int mi = 0; mi < 2; mi++)
#pragma unroll
                for (int ni = 0; ni < 4; ni++)
                    mma_tf32(acc[mi][ni], af[mi], bf[ni]);
        }
        if (has_next) {
            float* an = As + (buf ^ 1) * APERM;
            float* bn = Bs + (buf ^ 1) * APERM;
#pragma unroll
            for (int i = 0; i < 2; i++) {
                a_store4(an, abase[i], rA[i]);
                b_store4(bn, bbase[i], rB[i]);
            }
            __syncthreads();
            buf ^= 1;
        }
    }

#pragma unroll
    for (int mi = 0; mi < 2; mi++) {
        int r0 = (wid & 3) * 32 + mi * 16 + g;
        int rr[2] = { rid[r0], rid[r0 + 8] };
#pragma unroll
        for (int half = 0; half < 2; half++) {
            int r = rr[half];
            if (r < 0) continue;
#pragma unroll
            for (int ni = 0; ni < 4; ni++) {
                int col = n0 + (wid >> 2) * 32 + ni * 8 + cc * 2;
                float2 v = make_float2(acc[mi][ni][half * 2], acc[mi][ni][half * 2 + 1]);
                if (addA) {
                    float2 a = *(const float2*)(addA + (size_t)r * ldc + col);
                    v.x += a.x; v.y += a.y;
                }
                if (addS) {
                    float w = scaleVec[r];
                    float2 s = *(const float2*)(addS + (size_t)r * ldc + col);
                    v.x += s.x * w; v.y += s.y * w;
                }
                *(float2*)(C + (size_t)r * ldc + col) = v;
            }
        }
    }
}

// ---------------- tf32 GEMM NN (512 thr), permuted smem ----------------
__global__ void __launch_bounds__(512) mma_nn(
    const float* __restrict__ A, int lda, long long sA,
    const float* __restrict__ B, int ldb, long long sB,
    float* __restrict__ C, int ldc, long long sC,
    int M, int N, int K, int kcap)
{
    extern __shared__ float smem[];
    float* As = smem;
    float* Bs = smem + 2 * APERM;

    int z = blockIdx.z;
    A += (size_t)z * sA; B += (size_t)z * sB; C += (size_t)z * sC;
    int m0 = blockIdx.y * TBM;
    int n0 = blockIdx.x * TBN;
    int Keff = kcap ? min(K, m0 + TBM) : K;

    int tid = threadIdx.x;
    int larow[2], lacol[2], abase[2];
    int lbrow[2], lbcol[2], bbase[2];
#pragma unroll
    for (int i = 0; i < 2; i++) {
        int idx = tid + i * 512;
        larow[i] = idx >> 3;
        lacol[i] = (idx & 7) * 4;
        abase[i] = a_perm_base(larow[i], lacol[i]);
        lbrow[i] = idx >> 5;          // k row 0..31
        lbcol[i] = (idx & 31) * 4;    // n 0..124
        int kr = lbrow[i];
        int kblk = kr >> 3, ccB = kr & 3, k4 = (kr >> 2) & 1;
        int nblk = lbcol[i] >> 3, g0 = lbcol[i] & 7;
        bbase[i] = (nblk * MBLK_STR + kblk * KBLK_STR + g0 * 4 + ccB) * 2 + k4;
    }

    float4 rA[2], rB[2];
#pragma unroll
    for (int i = 0; i < 2; i++) {
        rA[i] = *(const float4*)(A + (size_t)(m0 + larow[i]) * lda + lacol[i]);
        rB[i] = *(const float4*)(B + (size_t)lbrow[i] * ldb + n0 + lbcol[i]);
    }
#pragma unroll
    for (int i = 0; i < 2; i++) {
        a_store4(As, abase[i], rA[i]);
        // B store: consecutive n -> g increments -> stride 8 floats
        Bs[bbase[i]]      = __uint_as_float(f2tf(rB[i].x));
        Bs[bbase[i] + 8]  = __uint_as_float(f2tf(rB[i].y));
        Bs[bbase[i] + 16] = __uint_as_float(f2tf(rB[i].z));
        Bs[bbase[i] + 24] = __uint_as_float(f2tf(rB[i].w));
    }
    __syncthreads();

    int lane = tid & 31, wid = tid >> 5;
    int wmblk = (wid & 3) * 2, wnblk = (wid >> 2) * 4;
    int g = lane >> 2, cc = lane & 3;
    int fragoff = g * 4 + cc;

    float acc[2][4][4];
#pragma unroll
    for (int mi = 0; mi < 2; mi++)
#pragma unroll
        for (int ni = 0; ni < 4; ni++)
#pragma unroll
            for (int j = 0; j < 4; j++) acc[mi][ni][j] = 0.f;

    int buf = 0;
    for (int kt = TBK; kt <= Keff; kt += TBK) {
        bool has_next = kt < Keff;
        if (has_next) {
#pragma unroll
            for (int i = 0; i < 2; i++) {
                rA[i] = *(const float4*)(A + (size_t)(m0 + larow[i]) * lda + kt + lacol[i]);
                rB[i] = *(const float4*)(B + (size_t)(kt + lbrow[i]) * ldb + n0 + lbcol[i]);
            }
        }
        const float* Ab = As + buf * APERM;
        const float* Bb = Bs + buf * APERM;
#pragma unroll
        for (int kblk = 0; kblk < 4; kblk++) {
            uint4 af[2];
            uint2 bf[4];
#pragma unroll
            for (int mi = 0; mi < 2; mi++)
                af[mi] = *(const uint4*)(Ab + ((wmblk + mi) * MBLK_STR + kblk * KBLK_STR + fragoff) * 4);
#pragma unroll
            for (int ni = 0; ni < 4; ni++)
                bf[ni] = *(const uint2*)(Bb + ((wnblk + ni) * MBLK_STR + kblk * KBLK_STR + fragoff) * 2);
#pragma unroll
            for (int mi = 0; mi < 2; mi++)
#pragma unroll
                for (int ni = 0; ni < 4; ni++)
                    mma_tf32(acc[mi][ni], af[mi], bf[ni]);
        }
        if (has_next) {
            float* an = As + (buf ^ 1) * APERM;
            float* bn = Bs + (buf ^ 1) * APERM;
#pragma unroll
            for (int i = 0; i < 2; i++) {
                a_store4(an, abase[i], rA[i]);
                bn[bbase[i]]      = __uint_as_float(f2tf(rB[i].x));
                bn[bbase[i] + 8]  = __uint_as_float(f2tf(rB[i].y));
                bn[bbase[i] + 16] = __uint_as_float(f2tf(rB[i].z));
                bn[bbase[i] + 24] = __uint_as_float(f2tf(rB[i].w));
            }
            __syncthreads();
            buf ^= 1;
        }
    }

#pragma unroll
    for (int mi = 0; mi < 2; mi++) {
        int r = m0 + (wid & 3) * 32 + mi * 16 + g;
#pragma unroll
        for (int ni = 0; ni < 4; ni++) {
            int col = n0 + (wid >> 2) * 32 + ni * 8 + cc * 2;
            *(float2*)(C + (size_t)r * ldc + col) = make_float2(acc[mi][ni][0], acc[mi][ni][1]);
            *(float2*)(C + (size_t)(r + 8) * ldc + col) = make_float2(acc[mi][ni][2], acc[mi][ni][3]);
        }
    }
}

// ---------------- rmsnorm ----------------
__global__ void rmsnorm_kernel(const float* __restrict__ x, const float* __restrict__ w,
                               float* __restrict__ out, int ncols) {
    int row = blockIdx.x;
    const float* xr = x + (size_t)row * ncols;
    float ss = 0.f;
    for (int i = threadIdx.x; i < ncols; i += blockDim.x) {
        float v = xr[i];
        ss += v * v;
    }
    float tot = blk_sum(ss);
    float inv = rsqrtf(tot / (float)ncols + EPS);
    float* orow = out + (size_t)row * ncols;
    for (int i = threadIdx.x; i < ncols; i += blockDim.x)
        orow[i] = xr[i] * inv * w[i];
}

// ---------------- per-head q/k rmsnorm + rope ----------------
__global__ void qk_norm_rope(float* __restrict__ qkv,
                             const float* __restrict__ qw, const float* __restrict__ kw) {
    int t = blockIdx.x, h = blockIdx.y, which = blockIdx.z;
    float* base = qkv + (size_t)t * (3 * H) + (size_t)which * H + (size_t)h * HD;
    int d = threadIdx.x;
    float v = base[d];
    float tot = blk_sum(v * v);
    float inv = rsqrtf(tot / (float)HD + EPS);
    const float* w = which ? kw : qw;
    float nv = v * inv * w[d];
    __shared__ float buf[HD];
    buf[d] = nv;
    __syncthreads();
    if (d < HD / 2) {
        int i = d;
        double invf = pow(10000.0, -2.0 * (double)i / (double)HD);
        double ang = (double)t * invf;
        float c = (float)cos(ang), s = (float)sin(ang);
        float t1 = buf[2 * i], t2 = buf[2 * i + 1];
        base[2 * i]     = t1 * c - t2 * s;
        base[2 * i + 1] = t1 * s + t2 * c;
    }
}

// ---------------- causal softmax ----------------
__global__ void softmax_causal(float* __restrict__ S) {
    int t = blockIdx.x, h = blockIdx.y;
    float* row = S + ((size_t)h * T + t) * T;
    int n = t + 1;
    int fill_end = min(T, ((t >> 7) + 1) << 7);
    const float scale = 0.08838834764831845f;
    float mx = -3.4e38f;
    for (int j = threadIdx.x; j < n; j += blockDim.x)
        mx = fmaxf(mx, row[j] * scale);
    mx = blk_max(mx);
    float sum = 0.f;
    for (int j = threadIdx.x; j < n; j += blockDim.x) {
        float e = expf(row[j] * scale - mx);
        row[j] = e;
        sum += e;
    }
    sum = blk_sum(sum);
    float invs = 1.f / sum;
    for (int j = threadIdx.x; j < n; j += blockDim.x) row[j] *= invs;
    for (int j = n + (int)threadIdx.x; j < fill_end; j += blockDim.x) row[j] = 0.f;
}

// ---------------- elementwise ----------------
__global__ void silu_mul(const float* __restrict__ gu, float* __restrict__ act) {
    int idx = blockIdx.x * blockDim.x + threadIdx.x;
    if (idx >= T * II) return;
    int t = idx / II, i = idx % II;
    float g = gu[(size_t)t * I2 + i];
    float u = gu[(size_t)t * I2 + II + i];
    act[(size_t)t * II + i] = (g / (1.f + expf(-g))) * u;
}

// ---------------- routing ----------------
__global__ void gate_logits(const float* __restrict__ h2, const float* __restrict__ gw,
                            float* __restrict__ logits) {
    int t = blockIdx.x;
    __shared__ float xs[H];
    for (int i = threadIdx.x; i < H; i += blockDim.x) xs[i] = h2[(size_t)t * H + i];
    __syncthreads();
    int warp = threadIdx.x >> 5, lane = threadIdx.x & 31;
    for (int e = warp; e < NE; e += (blockDim.x >> 5)) {
        const float* w = gw + (size_t)e * H;
        float s = 0.f;
        for (int k = lane; k < H; k += 32) s += xs[k] * w[k];
#pragma unroll
        for (int o = 16; o; o >>= 1) s += __shfl_xor_sync(0xffffffffu, s, o);
        if (lane == 0) logits[(size_t)t * NE + e] = s;
    }
}

__global__ void route_topk(const float* __restrict__ logits, float* __restrict__ topw,
                           int* __restrict__ topi) {
    int t = blockIdx.x * blockDim.x + threadIdx.x;
    if (t >= T) return;
    float mx = -3.4e38f;
    int mi = 0;
#pragma unroll
    for (int e = 0; e < NE; e++) {
        float l = logits[(size_t)t * NE + e];
        if (l > mx) { mx = l; mi = e; }
    }
    float s = 0.f;
#pragma unroll
    for (int e = 0; e < NE; e++) s += expf(logits[(size_t)t * NE + e] - mx);
    topw[t] = 1.f / s;
    topi[t] = mi;
}

__global__ void zero_counts(int* c) {
    if (threadIdx.x < NE) c[threadIdx.x] = 0;
}

__global__ void build_route(const int* __restrict__ topi, int* __restrict__ counts,
                            int* __restrict__ rows) {
    int t = blockIdx.x * blockDim.x + threadIdx.x;
    if (t >= T) return;
    int e = topi[t];
    int p = atomicAdd(&counts[e], 1);
    rows[(size_t)e * T + p] = t;
}

// ---------------- host ----------------
#define SYM(p, s) do { void* _v; cudaGetSymbolAddress(&_v, s); p = (decltype(p))_v; } while (0)

extern "C" void kernel_launch(void* const* d_in, const int* in_sizes, int n_in,
                              void* d_out, int out_size) {
    const float* x      = (const float*)d_in[0];
    const float* ln1    = (const float*)d_in[1];
    const float* qkv_w  = (const float*)d_in[2];
    const float* qlnw   = (const float*)d_in[3];
    const float* klnw   = (const float*)d_in[4];
    const float* o_w    = (const float*)d_in[5];
    const float* ln2    = (const float*)d_in[6];
    const float* gate_w = (const float*)d_in[7];
    const float* egu    = (const float*)d_in[8];
    const float* edown  = (const float*)d_in[9];
    const float* sguw   = (const float*)d_in[10];
    const float* sdw    = (const float*)d_in[11];
    float* out = (float*)d_out;

    float *h, *qkv, *S, *attn, *x2, *h2, *logits, *topw, *gu, *act, *moe, *sgu, *sact;
    int *topi, *counts, *rows;
    SYM(h, g_h); SYM(qkv, g_qkv); SYM(S, g_S); SYM(attn, g_attn);
    SYM(x2, g_x2); SYM(h2, g_h2); SYM(logits, g_logits); SYM(topw, g_topw);
    SYM(gu, g_gu); SYM(act, g_act); SYM(moe, g_moe); SYM(sgu, g_sgu); SYM(sact, g_sact);
    SYM(topi, g_topi); SYM(counts, g_counts); SYM(rows, g_rows);

    const int GSMEM = 4 * APERM * 4;   // 68096 B
    cudaFuncSetAttribute(mma_nt, cudaFuncAttributeMaxDynamicSharedMemorySize, GSMEM);
    cudaFuncSetAttribute(mma_nn, cudaFuncAttributeMaxDynamicSharedMemorySize, GSMEM);

    rmsnorm_kernel<<<T, 256>>>(x, ln1, h, H);
    mma_nt<<<dim3(3 * H / TBN, T / TBM, 1), 512, GSMEM>>>(h, H, 0, qkv_w, H, 0, qkv, 3 * H, 0,
                                                          T, 3 * H, H, 0, 0, 0, 0, 0, 0);
    qk_norm_rope<<<dim3(T, NH, 2), HD>>>(qkv, qlnw, klnw);
    mma_nt<<<dim3(T / TBN, T / TBM, NH), 512, GSMEM>>>(qkv, 3 * H, HD, qkv + H, 3 * H, HD,
                                                       S, T, (long long)T * T, T, T, HD,
                                                       0, 0, 1, 0, 0, 0);
    softmax_causal<<<dim3(T, NH), 256>>>(S);
    mma_nn<<<dim3(HD / TBN, T / TBM, NH), 512, GSMEM>>>(S, T, (long long)T * T, qkv + 2 * H, 3 * H, HD,
                                                        attn, H, HD, T, HD, T, 1);
    mma_nt<<<dim3(H / TBN, T / TBM, 1), 512, GSMEM>>>(attn, H, 0, o_w, H, 0, x2, H, 0,
                                                      T, H, H, 0, 0, 0, x, 0, 0);
    rmsnorm_kernel<<<T, 256>>>(x2, ln2, h2, H);
    gate_logits<<<T, 256>>>(h2, gate_w, logits);
    route_topk<<<(T + 255) / 256, 256>>>(logits, topw, topi);
    zero_counts<<<1, 32>>>(counts);
    build_route<<<(T + 255) / 256, 256>>>(topi, counts, rows);
    mma_nt<<<dim3(I2 / TBN, T / TBM, NE), 512, GSMEM>>>(h2, H, 0, egu, H, (long long)I2 * H,
                                                        gu, I2, 0, T, I2, H, rows, counts, 0, 0, 0, 0);
    silu_mul<<<(T * II + 255) / 256, 256>>>(gu, act);
    mma_nt<<<dim3(H / TBN, T / TBM, NE), 512, GSMEM>>>(act, II, 0, edown, II, (long long)H * II,
                                                       moe, H, 0, T, H, II, rows, counts, 0, 0, 0, 0);
    mma_nt<<<dim3(I2 / TBN, T / TBM, 1), 512, GSMEM>>>(h2, H, 0, sguw, H, 0, sgu, I2, 0,
                                                       T, I2, H, 0, 0, 0, 0, 0, 0);
    silu_mul<<<(T * II + 255) / 256, 256>>>(sgu, sact);
    mma_nt<<<dim3(H / TBN, T / TBM, 1), 512, GSMEM>>>(sact, II, 0, sdw, II, 0, out, H, 0,
                                                      T, H, II, 0, 0, 0, x2, moe, topw);
}

// round 8
// speedup vs baseline: 4.2935x; 1.4148x over previous
#include <cuda_runtime.h>
#include <math.h>
#include <stdint.h>

#define T  2048
#define H  2048
#define NH 16
#define HD 128
#define NE 16
#define II 2048
#define I2 4096
#define EPS 1e-6f

#define TBM 128
#define TBN 128
#define TBK 64
// permuted-layout constants per 32-k half-tile (proven R4 layout)
#define KBLK_STR 33
#define MBLK_STR 133
#define APH 4256                 // floats per matrix per 32-k half
#define ATILE64 (2 * APH)        // floats per matrix per 64-k stage
#define GSMEM (4 * ATILE64 * 4)  // 136192 bytes

// ---------------- scratch ----------------
__device__ float g_h[(size_t)T * H];
__device__ float g_qkv[(size_t)T * 3 * H];
__device__ float g_S[(size_t)NH * T * T];
__device__ float g_attn[(size_t)T * H];
__device__ float g_x2[(size_t)T * H];
__device__ float g_h2[(size_t)T * H];
__device__ float g_logits[(size_t)T * NE];
__device__ float g_topw[T];
__device__ int   g_topi[T];
__device__ int   g_counts[NE];
__device__ int   g_rows[(size_t)NE * T];
__device__ float g_gu[(size_t)T * I2];
__device__ float g_act[(size_t)T * II];
__device__ float g_moe[(size_t)T * H];
__device__ float g_sgu[(size_t)T * I2];
__device__ float g_sact[(size_t)T * II];
__device__ float g_cos[(size_t)T * (HD / 2)];
__device__ float g_sin[(size_t)T * (HD / 2)];

// ---------------- helpers ----------------
__device__ __forceinline__ uint32_t f2tf(float x) {
    uint32_t u;
    asm("cvt.rna.tf32.f32 %0, %1;" : "=r"(u) : "f"(x));
    return u;
}

__device__ __forceinline__ void mma_tf32(float c[4], uint4 a, uint2 b) {
    asm volatile("mma.sync.aligned.m16n8k8.row.col.f32.tf32.tf32.f32 "
                 "{%0,%1,%2,%3}, {%4,%5,%6,%7}, {%8,%9}, {%0,%1,%2,%3};"
                 : "+f"(c[0]), "+f"(c[1]), "+f"(c[2]), "+f"(c[3])
                 : "r"(a.x), "r"(a.y), "r"(a.z), "r"(a.w), "r"(b.x), "r"(b.y));
}

__device__ __forceinline__ float blk_sum(float v) {
    __shared__ float sh[33];
    __syncthreads();
    int lane = threadIdx.x & 31, w = threadIdx.x >> 5;
#pragma unroll
    for (int o = 16; o; o >>= 1) v += __shfl_xor_sync(0xffffffffu, v, o);
    if (lane == 0) sh[w] = v;
    __syncthreads();
    if (threadIdx.x < 32) {
        int nw = (blockDim.x + 31) >> 5;
        float r = (threadIdx.x < nw) ? sh[threadIdx.x] : 0.f;
#pragma unroll
        for (int o = 16; o; o >>= 1) r += __shfl_xor_sync(0xffffffffu, r, o);
        if (threadIdx.x == 0) sh[32] = r;
    }
    __syncthreads();
    return sh[32];
}

__device__ __forceinline__ float blk_max(float v) {
    __shared__ float sh[33];
    __syncthreads();
    int lane = threadIdx.x & 31, w = threadIdx.x >> 5;
#pragma unroll
    for (int o = 16; o; o >>= 1) v = fmaxf(v, __shfl_xor_sync(0xffffffffu, v, o));
    if (lane == 0) sh[w] = v;
    __syncthreads();
    if (threadIdx.x < 32) {
        int nw = (blockDim.x + 31) >> 5;
        float r = (threadIdx.x < nw) ? sh[threadIdx.x] : -3.4e38f;
#pragma unroll
        for (int o = 16; o; o >>= 1) r = fmaxf(r, __shfl_xor_sync(0xffffffffu, r, o));
        if (threadIdx.x == 0) sh[32] = r;
    }
    __syncthreads();
    return sh[32];
}

// permuted layout within one 32-k half (k0 in [0,32))
__device__ __forceinline__ int a_perm_base(int r, int k0) {
    int mblk = r >> 4, g = r & 7, half = (r >> 3) & 1;
    int kblk = k0 >> 3, k4 = (k0 >> 2) & 1;
    return (mblk * MBLK_STR + kblk * KBLK_STR + g * 4) * 4 + (half + 2 * k4);
}
__device__ __forceinline__ int b_perm_base(int r, int k0) {
    int nblk = r >> 3, g = r & 7;
    int kblk = k0 >> 3, k4 = (k0 >> 2) & 1;
    return (nblk * MBLK_STR + kblk * KBLK_STR + g * 4) * 2 + k4;
}
__device__ __forceinline__ void a_store4(float* As, int base, float4 v) {
    As[base]      = __uint_as_float(f2tf(v.x));
    As[base + 4]  = __uint_as_float(f2tf(v.y));
    As[base + 8]  = __uint_as_float(f2tf(v.z));
    As[base + 12] = __uint_as_float(f2tf(v.w));
}
__device__ __forceinline__ void b_store4(float* Bs, int base, float4 v) {
    Bs[base]     = __uint_as_float(f2tf(v.x));
    Bs[base + 2] = __uint_as_float(f2tf(v.y));
    Bs[base + 4] = __uint_as_float(f2tf(v.z));
    Bs[base + 6] = __uint_as_float(f2tf(v.w));
}

__device__ __forceinline__ void load_frags(const float* Ab, const float* Bb, int sub,
                                           int wmblk, int wnblk, int fragoff,
                                           uint4 af[2], uint2 bf[4]) {
    int khalf = sub >> 2, kblk = sub & 3;
    const float* Ah = Ab + khalf * APH;
    const float* Bh = Bb + khalf * APH;
#pragma unroll
    for (int mi = 0; mi < 2; mi++)
        af[mi] = *(const uint4*)(Ah + ((wmblk + mi) * MBLK_STR + kblk * KBLK_STR + fragoff) * 4);
#pragma unroll
    for (int ni = 0; ni < 4; ni++)
        bf[ni] = *(const uint2*)(Bh + ((wnblk + ni) * MBLK_STR + kblk * KBLK_STR + fragoff) * 2);
}

// ---------------- tf32 GEMM NT (512 thr), TBK=64, frag double-buffered ----------------
__global__ void __launch_bounds__(512) mma_nt(
    const float* __restrict__ A, int lda, long long sA,
    const float* __restrict__ B, int ldb, long long sB,
    float* __restrict__ C, int ldc, long long sC,
    int M, int N, int K,
    const int* __restrict__ rowsAll, const int* __restrict__ cntAll,
    int causal,
    const float* __restrict__ addA,
    const float* __restrict__ addS, const float* __restrict__ scaleVec)
{
    extern __shared__ float smem[];
    float* As = smem;
    float* Bs = smem + 2 * ATILE64;
    __shared__ int rid[TBM];

    int z = blockIdx.z;
    A += (size_t)z * sA; B += (size_t)z * sB; C += (size_t)z * sC;
    const int* rows = rowsAll ? rowsAll + (size_t)z * M : 0;
    int Mv = cntAll ? cntAll[z] : M;
    int m0 = blockIdx.y * TBM;
    if (m0 >= Mv) return;
    int n0 = blockIdx.x * TBN;
    if (causal && n0 > m0) return;

    int tid = threadIdx.x;
    if (tid < TBM) {
        int gm = m0 + tid;
        rid[tid] = rows ? (gm < Mv ? rows[gm] : -1) : gm;
    }
    __syncthreads();

    int lrow[4], lcol[4], ra[4], abase[4], bbase[4];
#pragma unroll
    for (int i = 0; i < 4; i++) {
        int idx = tid + i * 512;
        lrow[i] = idx >> 4;
        lcol[i] = (idx & 15) * 4;
        ra[i] = rid[lrow[i]];
        int khalf = lcol[i] >> 5, k0 = lcol[i] & 31;
        abase[i] = khalf * APH + a_perm_base(lrow[i], k0);
        bbase[i] = khalf * APH + b_perm_base(lrow[i], k0);
    }

    float4 rA[4], rB[4];
    const float4 z4 = make_float4(0.f, 0.f, 0.f, 0.f);
#pragma unroll
    for (int i = 0; i < 4; i++) {
        rA[i] = (ra[i] >= 0) ? *(const float4*)(A + (size_t)ra[i] * lda + lcol[i]) : z4;
        rB[i] = *(const float4*)(B + (size_t)(n0 + lrow[i]) * ldb + lcol[i]);
    }
#pragma unroll
    for (int i = 0; i < 4; i++) {
        a_store4(As, abase[i], rA[i]);
        b_store4(Bs, bbase[i], rB[i]);
    }
    __syncthreads();

    int lane = tid & 31, wid = tid >> 5;
    int wmblk = (wid & 3) * 2;
    int wnblk = (wid >> 2) * 4;
    int g = lane >> 2, cc = lane & 3;
    int fragoff = g * 4 + cc;

    float acc[2][4][4];
#pragma unroll
    for (int mi = 0; mi < 2; mi++)
#pragma unroll
        for (int ni = 0; ni < 4; ni++)
#pragma unroll
            for (int j = 0; j < 4; j++) acc[mi][ni][j] = 0.f;

    uint4 afb[2][2];
    uint2 bfb[2][4];
    int nt = K >> 6;
    for (int it = 0; it < nt; it++) {
        int buf = it & 1;
        const float* Ab = As + buf * ATILE64;
        const float* Bb = Bs + buf * ATILE64;
        load_frags(Ab, Bb, 0, wmblk, wnblk, fragoff, afb[0], bfb[0]);
        bool has_next = (it + 1) < nt;
        if (has_next) {
            int kt = (it + 1) << 6;
#pragma unroll
            for (int i = 0; i < 4; i++) {
                rA[i] = (ra[i] >= 0) ? *(const float4*)(A + (size_t)ra[i] * lda + kt + lcol[i]) : z4;
                rB[i] = *(const float4*)(B + (size_t)(n0 + lrow[i]) * ldb + kt + lcol[i]);
            }
        }
#pragma unroll
        for (int s = 0; s < 8; s++) {
            int cur = s & 1;
            if (s < 7)
                load_frags(Ab, Bb, s + 1, wmblk, wnblk, fragoff, afb[cur ^ 1], bfb[cur ^ 1]);
#pragma unroll
            for (int mi = 0; mi < 2; mi++)
#pragma unroll
                for (int ni = 0; ni < 4; ni++)
                    mma_tf32(acc[mi][ni], afb[cur][mi], bfb[cur][ni]);
        }
        if (has_next) {
            float* an = As + (buf ^ 1) * ATILE64;
            float* bn = Bs + (buf ^ 1) * ATILE64;
#pragma unroll
            for (int i = 0; i < 4; i++) {
                a_store4(an, abase[i], rA[i]);
                b_store4(bn, bbase[i], rB[i]);
            }
            __syncthreads();
        }
    }

#pragma unroll
    for (int mi = 0; mi < 2; mi++) {
        int r0 = (wid & 3) * 32 + mi * 16 + g;
        int rr[2] = { rid[r0], rid[r0 + 8] };
#pragma unroll
        for (int half = 0; half < 2; half++) {
            int r = rr[half];
            if (r < 0) continue;
#pragma unroll
            for (int ni = 0; ni < 4; ni++) {
                int col = n0 + (wid >> 2) * 32 + ni * 8 + cc * 2;
                float2 v = make_float2(acc[mi][ni][half * 2], acc[mi][ni][half * 2 + 1]);
                if (addA) {
                    float2 a = *(const float2*)(addA + (size_t)r * ldc + col);
                    v.x += a.x; v.y += a.y;
                }
                if (addS) {
                    float w = scaleVec[r];
                    float2 s = *(const float2*)(addS + (size_t)r * ldc + col);
                    v.x += s.x * w; v.y += s.y * w;
                }
                *(float2*)(C + (size_t)r * ldc + col) = v;
            }
        }
    }
}

// ---------------- tf32 GEMM NN (512 thr), TBK=64 ----------------
__global__ void __launch_bounds__(512) mma_nn(
    const float* __restrict__ A, int lda, long long sA,
    const float* __restrict__ B, int ldb, long long sB,
    float* __restrict__ C, int ldc, long long sC,
    int M, int N, int K, int kcap)
{
    extern __shared__ float smem[];
    float* As = smem;
    float* Bs = smem + 2 * ATILE64;

    int z = blockIdx.z;
    A += (size_t)z * sA; B += (size_t)z * sB; C += (size_t)z * sC;
    int m0 = blockIdx.y * TBM;
    int n0 = blockIdx.x * TBN;
    int Keff = kcap ? min(K, m0 + TBM) : K;

    int tid = threadIdx.x;
    int larow[4], lacol[4], abase[4];
    int lbkr[4], lbng[4], bbase[4];
#pragma unroll
    for (int i = 0; i < 4; i++) {
        int idx = tid + i * 512;
        larow[i] = idx >> 4;
        lacol[i] = (idx & 15) * 4;
        int khalfA = lacol[i] >> 5, k0A = lacol[i] & 31;
        abase[i] = khalfA * APH + a_perm_base(larow[i], k0A);
        lbkr[i] = idx >> 5;
        lbng[i] = (idx & 31) * 4;
        int khalfB = lbkr[i] >> 5, kr = lbkr[i] & 31;
        int kblk = kr >> 3, ccB = kr & 3, k4 = (kr >> 2) & 1;
        int nblk = lbng[i] >> 3, g0 = lbng[i] & 7;
        bbase[i] = khalfB * APH + (nblk * MBLK_STR + kblk * KBLK_STR + g0 * 4 + ccB) * 2 + k4;
    }

    float4 rA[4], rB[4];
#pragma unroll
    for (int i = 0; i < 4; i++) {
        rA[i] = *(const float4*)(A + (size_t)(m0 + larow[i]) * lda + lacol[i]);
        rB[i] = *(const float4*)(B + (size_t)lbkr[i] * ldb + n0 + lbng[i]);
    }
#pragma unroll
    for (int i = 0; i < 4; i++) {
        a_store4(As, abase[i], rA[i]);
        Bs[bbase[i]]      = __uint_as_float(f2tf(rB[i].x));
        Bs[bbase[i] + 8]  = __uint_as_float(f2tf(rB[i].y));
        Bs[bbase[i] + 16] = __uint_as_float(f2tf(rB[i].z));
        Bs[bbase[i] + 24] = __uint_as_float(f2tf(rB[i].w));
    }
    __syncthreads();

    int lane = tid & 31, wid = tid >> 5;
    int wmblk = (wid & 3) * 2, wnblk = (wid >> 2) * 4;
    int g = lane >> 2, cc = lane & 3;
    int fragoff = g * 4 + cc;

    float acc[2][4][4];
#pragma unroll
    for (int mi = 0; mi < 2; mi++)
#pragma unroll
        for (int ni = 0; ni < 4; ni++)
#pragma unroll
            for (int j = 0; j < 4; j++) acc[mi][ni][j] = 0.f;

    uint4 afb[2][2];
    uint2 bfb[2][4];
    int nt = Keff >> 6;
    for (int it = 0; it < nt; it++) {
        int buf = it & 1;
        const float* Ab = As + buf * ATILE64;
        const float* Bb = Bs + buf * ATILE64;
        load_frags(Ab, Bb, 0, wmblk, wnblk, fragoff, afb[0], bfb[0]);
        bool has_next = (it + 1) < nt;
        if (has_next) {
            int kt = (it + 1) << 6;
#pragma unroll
            for (int i = 0; i < 4; i++) {
                rA[i] = *(const float4*)(A + (size_t)(m0 + larow[i]) * lda + kt + lacol[i]);
                rB[i] = *(const float4*)(B + (size_t)(kt + lbkr[i]) * ldb + n0 + lbng[i]);
            }
        }
#pragma unroll
        for (int s = 0; s < 8; s++) {
            int cur = s & 1;
            if (s < 7)
                load_frags(Ab, Bb, s + 1, wmblk, wnblk, fragoff, afb[cur ^ 1], bfb[cur ^ 1]);
#pragma unroll
            for (int mi = 0; mi < 2; mi++)
#pragma unroll
                for (int ni = 0; ni < 4; ni++)
                    mma_tf32(acc[mi][ni], afb[cur][mi], bfb[cur][ni]);
        }
        if (has_next) {
            float* an = As + (buf ^ 1) * ATILE64;
            float* bn = Bs + (buf ^ 1) * ATILE64;
#pragma unroll
            for (int i = 0; i < 4; i++) {
                a_store4(an, abase[i], rA[i]);
                bn[bbase[i]]      = __uint_as_float(f2tf(rB[i].x));
                bn[bbase[i] + 8]  = __uint_as_float(f2tf(rB[i].y));
                bn[bbase[i] + 16] = __uint_as_float(f2tf(rB[i].z));
                bn[bbase[i] + 24] = __uint_as_float(f2tf(rB[i].w));
            }
            __syncthreads();
        }
    }

#pragma unroll
    for (int mi = 0; mi < 2; mi++) {
        int r = m0 + (wid & 3) * 32 + mi * 16 + g;
#pragma unroll
        for (int ni = 0; ni < 4; ni++) {
            int col = n0 + (wid >> 2) * 32 + ni * 8 + cc * 2;
            *(float2*)(C + (size_t)r * ldc + col) = make_float2(acc[mi][ni][0], acc[mi][ni][1]);
            *(float2*)(C + (size_t)(r + 8) * ldc + col) = make_float2(acc[mi][ni][2], acc[mi][ni][3]);
        }
    }
}

// ---------------- rope table (double precision, computed once per launch) -----------
__global__ void rope_table(float* __restrict__ ctab, float* __restrict__ stab) {
    int t = blockIdx.x, i = threadIdx.x;   // i < 64
    double invf = pow(10000.0, -2.0 * (double)i / (double)HD);
    double ang = (double)t * invf;
    ctab[t * (HD / 2) + i] = (float)cos(ang);
    stab[t * (HD / 2) + i] = (float)sin(ang);
}

// ---------------- rmsnorm ----------------
__global__ void rmsnorm_kernel(const float* __restrict__ x, const float* __restrict__ w,
                               float* __restrict__ out, int ncols) {
    int row = blockIdx.x;
    const float* xr = x + (size_t)row * ncols;
    float ss = 0.f;
    for (int i = threadIdx.x; i < ncols; i += blockDim.x) {
        float v = xr[i];
        ss += v * v;
    }
    float tot = blk_sum(ss);
    float inv = rsqrtf(tot / (float)ncols + EPS);
    float* orow = out + (size_t)row * ncols;
    for (int i = threadIdx.x; i < ncols; i += blockDim.x)
        orow[i] = xr[i] * inv * w[i];
}

// ---------------- per-head q/k rmsnorm + rope (table lookup) ----------------
__global__ void qk_norm_rope(float* __restrict__ qkv,
                             const float* __restrict__ qw, const float* __restrict__ kw,
                             const float* __restrict__ ctab, const float* __restrict__ stab) {
    int t = blockIdx.x, h = blockIdx.y, which = blockIdx.z;
    float* base = qkv + (size_t)t * (3 * H) + (size_t)which * H + (size_t)h * HD;
    int d = threadIdx.x;
    float v = base[d];
    float tot = blk_sum(v * v);
    float inv = rsqrtf(tot / (float)HD + EPS);
    const float* w = which ? kw : qw;
    float nv = v * inv * w[d];
    __shared__ float buf[HD];
    buf[d] = nv;
    __syncthreads();
    if (d < HD / 2) {
        int i = d;
        float c = ctab[t * (HD / 2) + i];
        float s = stab[t * (HD / 2) + i];
        float t1 = buf[2 * i], t2 = buf[2 * i + 1];
        base[2 * i]     = t1 * c - t2 * s;
        base[2 * i + 1] = t1 * s + t2 * c;
    }
}

// ---------------- causal softmax ----------------
__global__ void softmax_causal(float* __restrict__ S) {
    int t = blockIdx.x, h = blockIdx.y;
    float* row = S + ((size_t)h * T + t) * T;
    int n = t + 1;
    int fill_end = min(T, ((t >> 7) + 1) << 7);
    const float scale = 0.08838834764831845f;
    float mx = -3.4e38f;
    for (int j = threadIdx.x; j < n; j += blockDim.x)
        mx = fmaxf(mx, row[j] * scale);
    mx = blk_max(mx);
    float sum = 0.f;
    for (int j = threadIdx.x; j < n; j += blockDim.x) {
        float e = expf(row[j] * scale - mx);
        row[j] = e;
        sum += e;
    }
    sum = blk_sum(sum);
    float invs = 1.f / sum;
    for (int j = threadIdx.x; j < n; j += blockDim.x) row[j] *= invs;
    for (int j = n + (int)threadIdx.x; j < fill_end; j += blockDim.x) row[j] = 0.f;
}

// ---------------- elementwise ----------------
__global__ void silu_mul(const float* __restrict__ gu, float* __restrict__ act) {
    int idx = blockIdx.x * blockDim.x + threadIdx.x;
    if (idx >= T * II) return;
    int t = idx / II, i = idx % II;
    float g = gu[(size_t)t * I2 + i];
    float u = gu[(size_t)t * I2 + II + i];
    act[(size_t)t * II + i] = (g / (1.f + expf(-g))) * u;
}

// ---------------- routing ----------------
__global__ void gate_logits(const float* __restrict__ h2, const float* __restrict__ gw,
                            float* __restrict__ logits) {
    int t = blockIdx.x;
    __shared__ float xs[H];
    for (int i = threadIdx.x; i < H; i += blockDim.x) xs[i] = h2[(size_t)t * H + i];
    __syncthreads();
    int warp = threadIdx.x >> 5, lane = threadIdx.x & 31;
    for (int e = warp; e < NE; e += (blockDim.x >> 5)) {
        const float* w = gw + (size_t)e * H;
        float s = 0.f;
        for (int k = lane; k < H; k += 32) s += xs[k] * w[k];
#pragma unroll
        for (int o = 16; o; o >>= 1) s += __shfl_xor_sync(0xffffffffu, s, o);
        if (lane == 0) logits[(size_t)t * NE + e] = s;
    }
}

__global__ void route_topk(const float* __restrict__ logits, float* __restrict__ topw,
                           int* __restrict__ topi) {
    int t = blockIdx.x * blockDim.x + threadIdx.x;
    if (t >= T) return;
    float mx = -3.4e38f;
    int mi = 0;
#pragma unroll
    for (int e = 0; e < NE; e++) {
        float l = logits[(size_t)t * NE + e];
        if (l > mx) { mx = l; mi = e; }
    }
    float s = 0.f;
#pragma unroll
    for (int e = 0; e < NE; e++) s += expf(logits[(size_t)t * NE + e] - mx);
    topw[t] = 1.f / s;
    topi[t] = mi;
}

__global__ void zero_counts(int* c) {
    if (threadIdx.x < NE) c[threadIdx.x] = 0;
}

__global__ void build_route(const int* __restrict__ topi, int* __restrict__ counts,
                            int* __restrict__ rows) {
    int t = blockIdx.x * blockDim.x + threadIdx.x;
    if (t >= T) return;
    int e = topi[t];
    int p = atomicAdd(&counts[e], 1);
    rows[(size_t)e * T + p] = t;
}

// ---------------- host ----------------
#define SYM(p, s) do { void* _v; cudaGetSymbolAddress(&_v, s); p = (decltype(p))_v; } while (0)

extern "C" void kernel_launch(void* const* d_in, const int* in_sizes, int n_in,
                              void* d_out, int out_size) {
    const float* x      = (const float*)d_in[0];
    const float* ln1    = (const float*)d_in[1];
    const float* qkv_w  = (const float*)d_in[2];
    const float* qlnw   = (const float*)d_in[3];
    const float* klnw   = (const float*)d_in[4];
    const float* o_w    = (const float*)d_in[5];
    const float* ln2    = (const float*)d_in[6];
    const float* gate_w = (const float*)d_in[7];
    const float* egu    = (const float*)d_in[8];
    const float* edown  = (const float*)d_in[9];
    const float* sguw   = (const float*)d_in[10];
    const float* sdw    = (const float*)d_in[11];
    float* out = (float*)d_out;

    float *h, *qkv, *S, *attn, *x2, *h2, *logits, *topw, *gu, *act, *moe, *sgu, *sact, *ctab, *stab;
    int *topi, *counts, *rows;
    SYM(h, g_h); SYM(qkv, g_qkv); SYM(S, g_S); SYM(attn, g_attn);
    SYM(x2, g_x2); SYM(h2, g_h2); SYM(logits, g_logits); SYM(topw, g_topw);
    SYM(gu, g_gu); SYM(act, g_act); SYM(moe, g_moe); SYM(sgu, g_sgu); SYM(sact, g_sact);
    SYM(topi, g_topi); SYM(counts, g_counts); SYM(rows, g_rows);
    SYM(ctab, g_cos); SYM(stab, g_sin);

    cudaFuncSetAttribute(mma_nt, cudaFuncAttributeMaxDynamicSharedMemorySize, GSMEM);
    cudaFuncSetAttribute(mma_nn, cudaFuncAttributeMaxDynamicSharedMemorySize, GSMEM);

    rope_table<<<T, HD / 2>>>(ctab, stab);
    rmsnorm_kernel<<<T, 256>>>(x, ln1, h, H);
    mma_nt<<<dim3(3 * H / TBN, T / TBM, 1), 512, GSMEM>>>(h, H, 0, qkv_w, H, 0, qkv, 3 * H, 0,
                                                          T, 3 * H, H, 0, 0, 0, 0, 0, 0);
    qk_norm_rope<<<dim3(T, NH, 2), HD>>>(qkv, qlnw, klnw, ctab, stab);
    mma_nt<<<dim3(T / TBN, T / TBM, NH), 512, GSMEM>>>(qkv, 3 * H, HD, qkv + H, 3 * H, HD,
                                                       S, T, (long long)T * T, T, T, HD,
                                                       0, 0, 1, 0, 0, 0);
    softmax_causal<<<dim3(T, NH), 256>>>(S);
    mma_nn<<<dim3(HD / TBN, T / TBM, NH), 512, GSMEM>>>(S, T, (long long)T * T, qkv + 2 * H, 3 * H, HD,
                                                        attn, H, HD, T, HD, T, 1);
    mma_nt<<<dim3(H / TBN, T / TBM, 1), 512, GSMEM>>>(attn, H, 0, o_w, H, 0, x2, H, 0,
                                                      T, H, H, 0, 0, 0, x, 0, 0);
    rmsnorm_kernel<<<T, 256>>>(x2, ln2, h2, H);
    gate_logits<<<T, 256>>>(h2, gate_w, logits);
    route_topk<<<(T + 255) / 256, 256>>>(logits, topw, topi);
    zero_counts<<<1, 32>>>(counts);
    build_route<<<(T + 255) / 256, 256>>>(topi, counts, rows);
    mma_nt<<<dim3(I2 / TBN, T / TBM, NE), 512, GSMEM>>>(h2, H, 0, egu, H, (long long)I2 * H,
                                                        gu, I2, 0, T, I2, H, rows, counts, 0, 0, 0, 0);
    silu_mul<<<(T * II + 255) / 256, 256>>>(gu, act);
    mma_nt<<<dim3(H / TBN, T / TBM, NE), 512, GSMEM>>>(act, II, 0, edown, II, (long long)H * II,
                                                       moe, H, 0, T, H, II, rows, counts, 0, 0, 0, 0);
    mma_nt<<<dim3(I2 / TBN, T / TBM, 1), 512, GSMEM>>>(h2, H, 0, sguw, H, 0, sgu, I2, 0,
                                                       T, I2, H, 0, 0, 0, 0, 0, 0);
    silu_mul<<<(T * II + 255) / 256, 256>>>(sgu, sact);
    mma_nt<<<dim3(H / TBN, T / TBM, 1), 512, GSMEM>>>(sact, II, 0, sdw, II, 0, out, H, 0,
                                                      T, H, II, 0, 0, 0, x2, moe, topw);
}